// round 1
// baseline (speedup 1.0000x reference)
#include <cuda_runtime.h>

#define N_WRD  2000
#define B_SZ   64
#define CSZ    128
#define V_PIX  256
#define EMB    32

// ---------------- scratch (device globals; no allocations allowed) ----------
__device__ float g_h0[B_SZ * 512];
__device__ float g_wcode[B_SZ * 6000];            // == (B*N_WRD, 3) rows
__device__ float g_vs[V_PIX * EMB];
__device__ float g_route[(size_t)B_SZ * V_PIX * N_WRD];   // (B, V, N) 131MB

// ---------------- kernel 1: h0 = relu(v @ w1 + b1)  (64 x 512) --------------
__global__ void k_h0(const float* __restrict__ v,
                     const float* __restrict__ w1,
                     const float* __restrict__ b1) {
    int b = blockIdx.x;
    int j = threadIdx.x;           // 512 threads
    float acc = b1[j];
#pragma unroll
    for (int i = 0; i < 7; i++) acc = fmaf(v[b * 7 + i], w1[i * 512 + j], acc);
    g_h0[b * 512 + j] = fmaxf(acc, 0.f);
}

// ---------------- kernel 2: wcode = h0 @ w2 + b2  (64 x 6000, K=512) --------
__global__ __launch_bounds__(256) void k_wcode(const float* __restrict__ w2,
                                               const float* __restrict__ b2) {
    __shared__ float As[64 * 33];
    __shared__ float Bs[32 * 68];
    int t = threadIdx.x;
    int tx = t & 15, ty = t >> 4;
    int n0 = blockIdx.x * 64;
    float acc[4][4] = {};
    for (int k0 = 0; k0 < 512; k0 += 32) {
        for (int i = t; i < 2048; i += 256) {
            int r = i >> 5, k = i & 31;
            As[r * 33 + k] = g_h0[r * 512 + k0 + k];
        }
        for (int i = t; i < 2048; i += 256) {
            int k = i >> 6, n = i & 63;
            int nn = n0 + n;
            Bs[k * 68 + n] = (nn < 6000) ? w2[(k0 + k) * 6000 + nn] : 0.f;
        }
        __syncthreads();
#pragma unroll
        for (int k = 0; k < 32; k++) {
            float a[4], bb[4];
#pragma unroll
            for (int i = 0; i < 4; i++) a[i] = As[(4 * ty + i) * 33 + k];
#pragma unroll
            for (int j = 0; j < 4; j++) bb[j] = Bs[k * 68 + 4 * tx + j];
#pragma unroll
            for (int i = 0; i < 4; i++)
#pragma unroll
                for (int j = 0; j < 4; j++) acc[i][j] = fmaf(a[i], bb[j], acc[i][j]);
        }
        __syncthreads();
    }
#pragma unroll
    for (int i = 0; i < 4; i++) {
        int r = 4 * ty + i;
#pragma unroll
        for (int j = 0; j < 4; j++) {
            int col = n0 + 4 * tx + j;
            if (col < 6000) g_wcode[r * 6000 + col] = acc[i][j] + b2[col];
        }
    }
}

// ---------------- kernel 3: vs = relu(vcode@w1+b1)@w2+b2  (256 x 32) --------
__global__ void k_vs(const float* __restrict__ w1, const float* __restrict__ b1,
                     const float* __restrict__ w2, const float* __restrict__ b2) {
    int v = threadIdx.x;           // 256 threads, 1 block
    float x = -1.f + (2.f / 15.f) * (float)(v >> 4);
    float y = -1.f + (2.f / 15.f) * (float)(v & 15);
    float h[128];
#pragma unroll 4
    for (int j = 0; j < 128; j++)
        h[j] = fmaxf(fmaf(x, w1[j], fmaf(y, w1[128 + j], b1[j])), 0.f);
    for (int e = 0; e < EMB; e++) {
        float acc = b2[e];
#pragma unroll 4
        for (int j = 0; j < 128; j++) acc = fmaf(h[j], w2[j * EMB + e], acc);
        g_vs[v * EMB + e] = acc;
    }
}

// ---------------- kernel 4: fused fc1->fc2->fca/fce->relation->softmax ------
// 64 rows per block, 512 threads, dynamic smem 185344 B.
#define AS_OFF   0          // 64*257 A -> H2 -> route staging
#define BS_OFF   16448      // 32*260 fc2 K-tile
#define VST_OFF  24768      // 32*257 vs transposed [j][v]
#define FCE_OFF  32992      // 256*32
#define FCEB_OFF 41184      // 32
#define FCA_OFF  41216      // 256
#define ES_OFF   41472      // 64*33 embeddings e[r][j]
#define WC_OFF   43584      // 64*3
#define F1W_OFF  43776      // 3*256
#define F1B_OFF  44544      // 256
#define RM_OFF   44800      // 64*8 softmax max partials
#define RS_OFF   45312      // 64*8 softmax sum partials
#define AP_OFF   45824      // 64*8 activation partials
#define SMEM_FLOATS 46336

__global__ __launch_bounds__(512, 1) void k_route(
    const float* __restrict__ fc1_w, const float* __restrict__ fc1_b,
    const float* __restrict__ fc2_w, const float* __restrict__ fc2_b,
    const float* __restrict__ fca_w, const float* __restrict__ fca_b,
    const float* __restrict__ fce_w, const float* __restrict__ fce_b) {
    extern __shared__ float sm[];
    float* As  = sm + AS_OFF;
    float* Bs  = sm + BS_OFF;
    float* vsT = sm + VST_OFF;
    float* fce = sm + FCE_OFF;
    float* fceb= sm + FCEB_OFF;
    float* fca = sm + FCA_OFF;
    float* e_s = sm + ES_OFF;
    float* wc  = sm + WC_OFF;
    float* f1w = sm + F1W_OFF;
    float* f1b = sm + F1B_OFF;
    float* redm= sm + RM_OFF;
    float* reds= sm + RS_OFF;
    float* actp= sm + AP_OFF;

    const int t = threadIdx.x;
    const int row0 = blockIdx.x * 64;

    // ---- phase 0: stage constants ----
    for (int i = t; i < 8192; i += 512) {            // vs -> vsT[j][v], stride 257
        int vv = i >> 5, j = i & 31;
        vsT[j * 257 + vv] = g_vs[i];
    }
    for (int i = t; i < 8192; i += 512) fce[i] = fce_w[i];
    if (t < 32) fceb[t] = fce_b[t];
    if (t < 256) fca[t] = fca_w[t];
    for (int i = t; i < 768; i += 512) f1w[i] = fc1_w[i];
    if (t >= 512 - 256) f1b[t - 256] = fc1_b[t - 256];
    for (int i = t; i < 192; i += 512) wc[i] = g_wcode[row0 * 3 + i];
    __syncthreads();

    // ---- phase 1: A[r][k] = relu(fc1(wcode_r))  (64 x 256) ----
    for (int i = t; i < 64 * 256; i += 512) {
        int r = i >> 8, k = i & 255;
        float a = f1b[k];
        a = fmaf(wc[r * 3 + 0], f1w[k],       a);
        a = fmaf(wc[r * 3 + 1], f1w[256 + k], a);
        a = fmaf(wc[r * 3 + 2], f1w[512 + k], a);
        As[r * 257 + k] = fmaxf(a, 0.f);
    }
    __syncthreads();

    // ---- phase 2: H2 = relu(A @ fc2 + b)  (GEMM 64x256, K=256) ----
    const int cg = t & 31;          // cols {4cg..+3} and {128+4cg..+3}
    const int rg = t >> 5;          // rows rg*4..rg*4+3
    float acc[4][8] = {};
    for (int kt = 0; kt < 8; kt++) {
        for (int i = t; i < 8192; i += 512) {
            int kk = i >> 8, c = i & 255;
            Bs[kk * 260 + c] = fc2_w[(kt * 32 + kk) * 256 + c];
        }
        __syncthreads();
#pragma unroll
        for (int kk = 0; kk < 32; kk++) {
            float4 b0 = *(const float4*)&Bs[kk * 260 + 4 * cg];
            float4 b1 = *(const float4*)&Bs[kk * 260 + 128 + 4 * cg];
            int kg = kt * 32 + kk;
#pragma unroll
            for (int i = 0; i < 4; i++) {
                float a = As[(rg * 4 + i) * 257 + kg];
                acc[i][0] = fmaf(a, b0.x, acc[i][0]);
                acc[i][1] = fmaf(a, b0.y, acc[i][1]);
                acc[i][2] = fmaf(a, b0.z, acc[i][2]);
                acc[i][3] = fmaf(a, b0.w, acc[i][3]);
                acc[i][4] = fmaf(a, b1.x, acc[i][4]);
                acc[i][5] = fmaf(a, b1.y, acc[i][5]);
                acc[i][6] = fmaf(a, b1.z, acc[i][6]);
                acc[i][7] = fmaf(a, b1.w, acc[i][7]);
            }
        }
        __syncthreads();
    }
    // write H2 back into As (A dead now)
#pragma unroll
    for (int i = 0; i < 4; i++) {
        int r = rg * 4 + i;
#pragma unroll
        for (int j = 0; j < 4; j++) {
            As[r * 257 + 4 * cg + j]       = fmaxf(acc[i][j]     + fc2_b[4 * cg + j],       0.f);
            As[r * 257 + 128 + 4 * cg + j] = fmaxf(acc[i][4 + j] + fc2_b[128 + 4 * cg + j], 0.f);
        }
    }
    __syncthreads();

    // ---- phase 3: e = H2 @ fce + b,  act partials = H2 . fca ----
    {
        int r = t >> 3, q = t & 7;          // r 0..63, q 0..7
        float p = 0.f;
        for (int k = q * 32; k < q * 32 + 32; k++) p = fmaf(As[r * 257 + k], fca[k], p);
        actp[r * 8 + q] = p;
        int j0 = q * 4;
        float e0 = fceb[j0], e1 = fceb[j0 + 1], e2 = fceb[j0 + 2], e3 = fceb[j0 + 3];
#pragma unroll 4
        for (int k = 0; k < 256; k++) {
            float h = As[r * 257 + k];
            e0 = fmaf(h, fce[k * 32 + j0 + 0], e0);
            e1 = fmaf(h, fce[k * 32 + j0 + 1], e1);
            e2 = fmaf(h, fce[k * 32 + j0 + 2], e2);
            e3 = fmaf(h, fce[k * 32 + j0 + 3], e3);
        }
        e_s[r * 33 + j0 + 0] = e0;
        e_s[r * 33 + j0 + 1] = e1;
        e_s[r * 33 + j0 + 2] = e2;
        e_s[r * 33 + j0 + 3] = e3;
    }
    __syncthreads();

    // ---- phase 4: relation + softmax * activation ----
    const int w   = t >> 5, lane = t & 31;
    const int v0  = (w & 7) * 32;
    const int rb  = (w >> 3) * 32;           // 0 or 32
    const int v   = v0 + lane;
    float vreg[32];
#pragma unroll
    for (int j = 0; j < 32; j++) vreg[j] = vsT[j * 257 + v];

    // pass 1: raw relation into As (H2 dead), warp-level max partials
    for (int rr = 0; rr < 32; rr++) {
        int r = rb + rr;
        float rel = 0.f;
#pragma unroll
        for (int j = 0; j < 32; j++) rel = fmaf(e_s[r * 33 + j], vreg[j], rel);
        As[r * 257 + v] = rel;
        float m = rel;
#pragma unroll
        for (int o = 16; o; o >>= 1) m = fmaxf(m, __shfl_xor_sync(0xffffffffu, m, o));
        if (lane == 0) redm[r * 8 + (w & 7)] = m;
    }
    __syncthreads();

    // pass 2: exp + sum partials
    for (int rr = 0; rr < 32; rr++) {
        int r = rb + rr;
        float m = redm[r * 8];
#pragma unroll
        for (int i = 1; i < 8; i++) m = fmaxf(m, redm[r * 8 + i]);
        float ex = __expf(As[r * 257 + v] - m);
        As[r * 257 + v] = ex;
        float s = ex;
#pragma unroll
        for (int o = 16; o; o >>= 1) s += __shfl_xor_sync(0xffffffffu, s, o);
        if (lane == 0) reds[r * 8 + (w & 7)] = s;
    }
    __syncthreads();

    // pass 3: scale by act/sum
    float fcab = fca_b[0];
    for (int rr = 0; rr < 32; rr++) {
        int r = rb + rr;
        float s = 0.f, ap = fcab;
#pragma unroll
        for (int i = 0; i < 8; i++) { s += reds[r * 8 + i]; ap += actp[r * 8 + i]; }
        float act = 1.f / (1.f + __expf(-ap));
        As[r * 257 + v] *= act / s;
    }
    __syncthreads();

    // ---- phase 5: coalesced write route (B, V, N) ----
    for (int i = t; i < 64 * 256; i += 512) {
        int vv = i >> 6, ii = i & 63;
        int row = row0 + ii;
        int bb = row / N_WRD;
        int n  = row - bb * N_WRD;
        g_route[((size_t)bb * 256 + vv) * N_WRD + n] = As[ii * 257 + vv];
    }
}

// ---------------- kernel 5: out[b] = VC[b](128x256) @ route[b](256x2000) ----
__global__ __launch_bounds__(256) void k_out(const float* __restrict__ vc,
                                             float* __restrict__ out) {
    __shared__ float As[128 * 33];
    __shared__ float Bs[32 * 132];
    const int bb = blockIdx.y;
    const int n0 = blockIdx.x * 128;
    const int t  = threadIdx.x;
    const int tx = t & 15, ty = t >> 4;
    const float* A  = vc + (size_t)bb * CSZ * V_PIX;
    const float* Rb = g_route + (size_t)bb * V_PIX * N_WRD;
    float acc[8][8] = {};
    for (int k0 = 0; k0 < 256; k0 += 32) {
        for (int i = t; i < 4096; i += 256) {
            int c = i >> 5, k = i & 31;
            As[c * 33 + k] = A[c * 256 + k0 + k];
        }
        for (int i = t; i < 4096; i += 256) {
            int k = i >> 7, n = i & 127;
            int nn = n0 + n;
            Bs[k * 132 + n] = (nn < N_WRD) ? Rb[(size_t)(k0 + k) * N_WRD + nn] : 0.f;
        }
        __syncthreads();
#pragma unroll
        for (int k = 0; k < 32; k++) {
            float a[8], b[8];
            float4 b0 = *(const float4*)&Bs[k * 132 + 4 * tx];
            float4 b1 = *(const float4*)&Bs[k * 132 + 64 + 4 * tx];
            b[0] = b0.x; b[1] = b0.y; b[2] = b0.z; b[3] = b0.w;
            b[4] = b1.x; b[5] = b1.y; b[6] = b1.z; b[7] = b1.w;
#pragma unroll
            for (int i = 0; i < 4; i++) {
                a[i]     = As[(4 * ty + i) * 33 + k];
                a[4 + i] = As[(64 + 4 * ty + i) * 33 + k];
            }
#pragma unroll
            for (int i = 0; i < 8; i++)
#pragma unroll
                for (int j = 0; j < 8; j++) acc[i][j] = fmaf(a[i], b[j], acc[i][j]);
        }
        __syncthreads();
    }
#pragma unroll
    for (int i = 0; i < 8; i++) {
        int c = (i < 4) ? (4 * ty + i) : (64 + 4 * ty + (i - 4));
        float* orow = out + ((size_t)bb * CSZ + c) * N_WRD;
        int n1 = n0 + 4 * tx;
        int n2 = n0 + 64 + 4 * tx;
        if (n1 < N_WRD) {
            float4 s; s.x = acc[i][0]; s.y = acc[i][1]; s.z = acc[i][2]; s.w = acc[i][3];
            *(float4*)&orow[n1] = s;
        }
        if (n2 < N_WRD) {
            float4 s; s.x = acc[i][4]; s.y = acc[i][5]; s.z = acc[i][6]; s.w = acc[i][7];
            *(float4*)&orow[n2] = s;
        }
    }
}

// ---------------- launch --------------------------------------------------
extern "C" void kernel_launch(void* const* d_in, const int* in_sizes, int n_in,
                              void* d_out, int out_size) {
    const float* view_cell = (const float*)d_in[0];
    const float* v         = (const float*)d_in[1];
    const float* w2c_w1    = (const float*)d_in[2];
    const float* w2c_b1    = (const float*)d_in[3];
    const float* w2c_w2    = (const float*)d_in[4];
    const float* w2c_b2    = (const float*)d_in[5];
    const float* fc1_w     = (const float*)d_in[6];
    const float* fc1_b     = (const float*)d_in[7];
    const float* fc2_w     = (const float*)d_in[8];
    const float* fc2_b     = (const float*)d_in[9];
    const float* fca_w     = (const float*)d_in[10];
    const float* fca_b     = (const float*)d_in[11];
    const float* fce_w     = (const float*)d_in[12];
    const float* fce_b     = (const float*)d_in[13];
    const float* vse_w1    = (const float*)d_in[14];
    const float* vse_b1    = (const float*)d_in[15];
    const float* vse_w2    = (const float*)d_in[16];
    const float* vse_b2    = (const float*)d_in[17];
    float* out = (float*)d_out;

    cudaFuncSetAttribute(k_route, cudaFuncAttributeMaxDynamicSharedMemorySize,
                         SMEM_FLOATS * 4);

    k_h0<<<B_SZ, 512>>>(v, w2c_w1, w2c_b1);
    k_wcode<<<(6000 + 63) / 64, 256>>>(w2c_w2, w2c_b2);
    k_vs<<<1, 256>>>(vse_w1, vse_b1, vse_w2, vse_b2);
    k_route<<<(B_SZ * N_WRD) / 64, 512, SMEM_FLOATS * 4>>>(
        fc1_w, fc1_b, fc2_w, fc2_b, fca_w, fca_b, fce_w, fce_b);
    dim3 gridO((N_WRD + 127) / 128, B_SZ);
    k_out<<<gridO, 256>>>(view_cell, out);
}

// round 2
// speedup vs baseline: 1.2771x; 1.2771x over previous
#include <cuda_runtime.h>

#define N_WRD  2000
#define B_SZ   64
#define CSZ    128
#define V_PIX  256
#define EMB    32

// ---------------- scratch (device globals; no allocations allowed) ----------
__device__ float g_h0[B_SZ * 512];
__device__ float g_wcode[B_SZ * 6000];            // (B*N_WRD, 3) rows flattened
__device__ float g_vs[V_PIX * EMB];
__device__ float g_e[(size_t)B_SZ * N_WRD * EMB]; // (B*N, 32) embeddings
__device__ float g_act[B_SZ * N_WRD];             // sigmoid activation

// ---------------- kernel 1: h0 = relu(v @ w1 + b1)  (64 x 512) --------------
__global__ void k_h0(const float* __restrict__ v,
                     const float* __restrict__ w1,
                     const float* __restrict__ b1) {
    int b = blockIdx.x;
    int j = threadIdx.x;           // 512 threads
    float acc = b1[j];
#pragma unroll
    for (int i = 0; i < 7; i++) acc = fmaf(v[b * 7 + i], w1[i * 512 + j], acc);
    g_h0[b * 512 + j] = fmaxf(acc, 0.f);
}

// ---------------- kernel 2: wcode = h0 @ w2 + b2  (64 x 6000, K=512) --------
__global__ __launch_bounds__(256) void k_wcode(const float* __restrict__ w2,
                                               const float* __restrict__ b2) {
    __shared__ float As[64 * 33];
    __shared__ float Bs[32 * 68];
    int t = threadIdx.x;
    int tx = t & 15, ty = t >> 4;
    int n0 = blockIdx.x * 64;
    float acc[4][4] = {};
    for (int k0 = 0; k0 < 512; k0 += 32) {
        for (int i = t; i < 2048; i += 256) {
            int r = i >> 5, k = i & 31;
            As[r * 33 + k] = g_h0[r * 512 + k0 + k];
        }
        for (int i = t; i < 2048; i += 256) {
            int k = i >> 6, n = i & 63;
            int nn = n0 + n;
            Bs[k * 68 + n] = (nn < 6000) ? w2[(k0 + k) * 6000 + nn] : 0.f;
        }
        __syncthreads();
#pragma unroll
        for (int k = 0; k < 32; k++) {
            float a[4], bb[4];
#pragma unroll
            for (int i = 0; i < 4; i++) a[i] = As[(4 * ty + i) * 33 + k];
#pragma unroll
            for (int j = 0; j < 4; j++) bb[j] = Bs[k * 68 + 4 * tx + j];
#pragma unroll
            for (int i = 0; i < 4; i++)
#pragma unroll
                for (int j = 0; j < 4; j++) acc[i][j] = fmaf(a[i], bb[j], acc[i][j]);
        }
        __syncthreads();
    }
#pragma unroll
    for (int i = 0; i < 4; i++) {
        int r = 4 * ty + i;
#pragma unroll
        for (int j = 0; j < 4; j++) {
            int col = n0 + 4 * tx + j;
            if (col < 6000) g_wcode[r * 6000 + col] = acc[i][j] + b2[col];
        }
    }
}

// ---------------- kernel 3: vs = relu(vcode@w1+b1)@w2+b2  (256 x 32) --------
__global__ void k_vs(const float* __restrict__ w1, const float* __restrict__ b1,
                     const float* __restrict__ w2, const float* __restrict__ b2) {
    int v = threadIdx.x;           // 256 threads, 1 block
    float x = -1.f + (2.f / 15.f) * (float)(v >> 4);
    float y = -1.f + (2.f / 15.f) * (float)(v & 15);
    float h[128];
#pragma unroll 4
    for (int j = 0; j < 128; j++)
        h[j] = fmaxf(fmaf(x, w1[j], fmaf(y, w1[128 + j], b1[j])), 0.f);
    for (int e = 0; e < EMB; e++) {
        float acc = b2[e];
#pragma unroll 4
        for (int j = 0; j < 128; j++) acc = fmaf(h[j], w2[j * EMB + e], acc);
        g_vs[v * EMB + e] = acc;
    }
}

// ---------------- kernel A: fc1 -> fc2 -> fce/fca  (128 rows / block) -------
// smem layout (floats):
#define A_AS    0          // 128*260 = 33280 : fc1 out, then H2
#define A_BS    33280      // 8320 : fc2 k-tile (32x260); later fce (256x32)
#define A_F1W   41600      // 768
#define A_F1B   42368      // 256
#define A_WC    42624      // 384
#define A_FCA   43008      // 256
#define A_ACTP  43264      // 512 (128*4)
#define A_SMEM  43776

__global__ __launch_bounds__(512, 1) void k_A(
    const float* __restrict__ fc1_w, const float* __restrict__ fc1_b,
    const float* __restrict__ fc2_w, const float* __restrict__ fc2_b,
    const float* __restrict__ fca_w, const float* __restrict__ fca_b,
    const float* __restrict__ fce_w, const float* __restrict__ fce_b) {
    extern __shared__ float sm[];
    float* As   = sm + A_AS;
    float* Bs   = sm + A_BS;
    float* f1w  = sm + A_F1W;
    float* f1b  = sm + A_F1B;
    float* wc   = sm + A_WC;
    float* fcaS = sm + A_FCA;
    float* actp = sm + A_ACTP;

    const int t = threadIdx.x;
    const int row0 = blockIdx.x * 128;

    // stage small constants + wcode rows
    for (int i = t; i < 768; i += 512) f1w[i] = fc1_w[i];
    if (t < 256) f1b[t] = fc1_b[t];
    else if (t < 512) fcaS[t - 256] = fca_w[t - 256];
    for (int i = t; i < 384; i += 512) wc[i] = g_wcode[row0 * 3 + i];
    __syncthreads();

    // phase 1: A[r][k] = relu(fc1(wcode_r))  (128 x 256)
    for (int i = t; i < 128 * 256; i += 512) {
        int r = i >> 8, k = i & 255;
        float a = f1b[k];
        a = fmaf(wc[r * 3 + 0], f1w[k],       a);
        a = fmaf(wc[r * 3 + 1], f1w[256 + k], a);
        a = fmaf(wc[r * 3 + 2], f1w[512 + k], a);
        As[r * 260 + k] = fmaxf(a, 0.f);
    }
    __syncthreads();

    // phase 2: H2 = relu(A @ fc2 + b)  (128x256, K=256), 8x8 microtiles
    const int tx = t & 31;          // cols 4tx..+3 and 128+4tx..+3
    const int ty = t >> 5;          // rows ty*8..ty*8+7
    float acc[8][8] = {};
    for (int kt = 0; kt < 8; kt++) {
        for (int i = t; i < 8192; i += 512) {
            int kk = i >> 8, c = i & 255;
            Bs[kk * 260 + c] = fc2_w[(kt * 32 + kk) * 256 + c];
        }
        __syncthreads();
#pragma unroll
        for (int kk = 0; kk < 32; kk++) {
            int kg = kt * 32 + kk;
            float4 b0 = *(const float4*)&Bs[kk * 260 + 4 * tx];
            float4 b1 = *(const float4*)&Bs[kk * 260 + 128 + 4 * tx];
            float a[8];
#pragma unroll
            for (int i = 0; i < 8; i++) a[i] = As[(ty * 8 + i) * 260 + kg];
#pragma unroll
            for (int i = 0; i < 8; i++) {
                acc[i][0] = fmaf(a[i], b0.x, acc[i][0]);
                acc[i][1] = fmaf(a[i], b0.y, acc[i][1]);
                acc[i][2] = fmaf(a[i], b0.z, acc[i][2]);
                acc[i][3] = fmaf(a[i], b0.w, acc[i][3]);
                acc[i][4] = fmaf(a[i], b1.x, acc[i][4]);
                acc[i][5] = fmaf(a[i], b1.y, acc[i][5]);
                acc[i][6] = fmaf(a[i], b1.z, acc[i][6]);
                acc[i][7] = fmaf(a[i], b1.w, acc[i][7]);
            }
        }
        __syncthreads();
    }
    // H2 (+bias, relu) back into As (A dead now)
#pragma unroll
    for (int i = 0; i < 8; i++) {
        int r = ty * 8 + i;
#pragma unroll
        for (int j = 0; j < 4; j++) {
            As[r * 260 + 4 * tx + j]       = fmaxf(acc[i][j]     + fc2_b[4 * tx + j],       0.f);
            As[r * 260 + 128 + 4 * tx + j] = fmaxf(acc[i][4 + j] + fc2_b[128 + 4 * tx + j], 0.f);
        }
    }
    __syncthreads();

    // phase 3: e = H2 @ fce + b (float4 weights), act partials
    for (int i = t; i < 8192; i += 512) Bs[i] = fce_w[i];   // fce [k][32]
    __syncthreads();
    {
        int r = t >> 2, q = t & 3, j0 = q * 8;
        float e[8];
#pragma unroll
        for (int j = 0; j < 8; j++) e[j] = fce_b[j0 + j];
#pragma unroll 2
        for (int k = 0; k < 256; k++) {
            float h = As[r * 260 + k];
            float4 f0 = *(const float4*)&Bs[k * 32 + j0];
            float4 f1 = *(const float4*)&Bs[k * 32 + j0 + 4];
            e[0] = fmaf(h, f0.x, e[0]);
            e[1] = fmaf(h, f0.y, e[1]);
            e[2] = fmaf(h, f0.z, e[2]);
            e[3] = fmaf(h, f0.w, e[3]);
            e[4] = fmaf(h, f1.x, e[4]);
            e[5] = fmaf(h, f1.y, e[5]);
            e[6] = fmaf(h, f1.z, e[6]);
            e[7] = fmaf(h, f1.w, e[7]);
        }
        float p = 0.f;
        for (int k = q * 64; k < q * 64 + 64; k++) p = fmaf(As[r * 260 + k], fcaS[k], p);
        actp[r * 4 + q] = p;

        size_t base = (size_t)(row0 + r) * 32 + j0;
        float4 s0, s1;
        s0.x = e[0]; s0.y = e[1]; s0.z = e[2]; s0.w = e[3];
        s1.x = e[4]; s1.y = e[5]; s1.z = e[6]; s1.w = e[7];
        *(float4*)&g_e[base]     = s0;
        *(float4*)&g_e[base + 4] = s1;
    }
    __syncthreads();
    if (t < 128) {
        float ap = fca_b[0] + actp[t * 4] + actp[t * 4 + 1] + actp[t * 4 + 2] + actp[t * 4 + 3];
        g_act[row0 + t] = 1.f / (1.f + __expf(-ap));
    }
}

// ---------------- kernel B: relation -> softmax -> route -> output GEMM ----
// block = (n-tile of 128 words, batch b), 256 threads. route stays in smem.
// smem layout (floats):
#define B_RT    0          // routeT[v][n]: 256*132 = 33792
#define B_VS    33792      // vs [v][32]: 8192
#define B_ES    41984      // e  [n][33]: 4224
#define B_VCT   46208      // vc k-tile transposed [v][c]: 32*132 = 4224
#define B_ACT   50432      // 128
#define B_RM    50560      // 128*9 = 1152
#define B_RS    51712      // 1152
#define B_SMEM  52864

__global__ __launch_bounds__(256, 1) void k_B(const float* __restrict__ vc_g,
                                              float* __restrict__ out) {
    extern __shared__ float sm[];
    float* routeT = sm + B_RT;
    float* vsS    = sm + B_VS;
    float* es     = sm + B_ES;
    float* vct    = sm + B_VCT;
    float* actS   = sm + B_ACT;
    float* redm   = sm + B_RM;
    float* reds   = sm + B_RS;

    const int t = threadIdx.x;
    const int w = t >> 5, lane = t & 31;
    const int n0 = blockIdx.x * 128;
    const int b  = blockIdx.y;

    // stage vs, e-tile (guarded), act
    for (int i = t; i < 8192; i += 256) vsS[i] = g_vs[i];
    for (int i = t; i < 128 * 32; i += 256) {
        int n = i >> 5, j = i & 31;
        int row = n0 + n;
        es[n * 33 + j] = (row < N_WRD) ? g_e[(size_t)(b * N_WRD + row) * 32 + j] : 0.f;
    }
    if (t < 128) {
        int row = n0 + t;
        actS[t] = (row < N_WRD) ? g_act[b * N_WRD + row] : 0.f;
    }
    __syncthreads();

    // pass 1: relation. lanes = n, warp w owns v in [32w, 32w+32).
    const int vbase = w * 32;
    for (int nc = 0; nc < 4; nc++) {
        int n = nc * 32 + lane;
        float e[32];
#pragma unroll
        for (int j = 0; j < 32; j++) e[j] = es[n * 33 + j];
        float mx = -1e30f;
#pragma unroll 4
        for (int vv = 0; vv < 32; vv++) {
            const float4* vr = (const float4*)&vsS[(vbase + vv) * 32];
            float rel = 0.f;
#pragma unroll
            for (int j4 = 0; j4 < 8; j4++) {
                float4 f = vr[j4];
                rel = fmaf(e[4 * j4 + 0], f.x, rel);
                rel = fmaf(e[4 * j4 + 1], f.y, rel);
                rel = fmaf(e[4 * j4 + 2], f.z, rel);
                rel = fmaf(e[4 * j4 + 3], f.w, rel);
            }
            routeT[(vbase + vv) * 132 + n] = rel;
            mx = fmaxf(mx, rel);
        }
        redm[n * 9 + w] = mx;
    }
    __syncthreads();

    // pass 2: exp + partial sums
    for (int nc = 0; nc < 4; nc++) {
        int n = nc * 32 + lane;
        float m = redm[n * 9];
#pragma unroll
        for (int i = 1; i < 8; i++) m = fmaxf(m, redm[n * 9 + i]);
        float s = 0.f;
#pragma unroll 4
        for (int vv = 0; vv < 32; vv++) {
            float x = __expf(routeT[(vbase + vv) * 132 + n] - m);
            routeT[(vbase + vv) * 132 + n] = x;
            s += x;
        }
        reds[n * 9 + w] = s;
    }
    __syncthreads();

    // pass 3: scale by act/sum
    for (int nc = 0; nc < 4; nc++) {
        int n = nc * 32 + lane;
        float s = 0.f;
#pragma unroll
        for (int i = 0; i < 8; i++) s += reds[n * 9 + i];
        float sc = actS[n] / s;
#pragma unroll 4
        for (int vv = 0; vv < 32; vv++) routeT[(vbase + vv) * 132 + n] *= sc;
    }
    __syncthreads();

    // GEMM: out[c][n] = sum_v VC[c][v] * routeT[v][n], 128c x 128n, K=256
    const int tx = t & 15;          // n cols 4tx..+3 and 64+4tx..+3
    const int ty = t >> 4;          // c rows 8ty..8ty+7
    float acc[8][8] = {};
    const float* A = vc_g + (size_t)b * CSZ * V_PIX;
    for (int k0 = 0; k0 < 256; k0 += 32) {
        for (int i = t; i < 4096; i += 256) {
            int c = i >> 5, vv = i & 31;
            vct[vv * 132 + c] = A[c * 256 + k0 + vv];
        }
        __syncthreads();
#pragma unroll
        for (int vv = 0; vv < 32; vv++) {
            int v = k0 + vv;
            float4 a0 = *(const float4*)&vct[vv * 132 + 8 * ty];
            float4 a1 = *(const float4*)&vct[vv * 132 + 8 * ty + 4];
            float4 b0 = *(const float4*)&routeT[v * 132 + 4 * tx];
            float4 b1 = *(const float4*)&routeT[v * 132 + 64 + 4 * tx];
            float a[8] = {a0.x, a0.y, a0.z, a0.w, a1.x, a1.y, a1.z, a1.w};
            float bb[8] = {b0.x, b0.y, b0.z, b0.w, b1.x, b1.y, b1.z, b1.w};
#pragma unroll
            for (int i = 0; i < 8; i++)
#pragma unroll
                for (int j = 0; j < 8; j++) acc[i][j] = fmaf(a[i], bb[j], acc[i][j]);
        }
        __syncthreads();
    }
    // store (2000 % 4 == 0 so float4 stores are all-valid or all-invalid)
#pragma unroll
    for (int i = 0; i < 8; i++) {
        int c = 8 * ty + i;
        float* orow = out + ((size_t)b * CSZ + c) * N_WRD;
        int n1 = n0 + 4 * tx;
        int n2 = n0 + 64 + 4 * tx;
        if (n1 + 3 < N_WRD) {
            float4 s; s.x = acc[i][0]; s.y = acc[i][1]; s.z = acc[i][2]; s.w = acc[i][3];
            *(float4*)&orow[n1] = s;
        }
        if (n2 + 3 < N_WRD) {
            float4 s; s.x = acc[i][4]; s.y = acc[i][5]; s.z = acc[i][6]; s.w = acc[i][7];
            *(float4*)&orow[n2] = s;
        }
    }
}

// ---------------- launch --------------------------------------------------
extern "C" void kernel_launch(void* const* d_in, const int* in_sizes, int n_in,
                              void* d_out, int out_size) {
    const float* view_cell = (const float*)d_in[0];
    const float* v         = (const float*)d_in[1];
    const float* w2c_w1    = (const float*)d_in[2];
    const float* w2c_b1    = (const float*)d_in[3];
    const float* w2c_w2    = (const float*)d_in[4];
    const float* w2c_b2    = (const float*)d_in[5];
    const float* fc1_w     = (const float*)d_in[6];
    const float* fc1_b     = (const float*)d_in[7];
    const float* fc2_w     = (const float*)d_in[8];
    const float* fc2_b     = (const float*)d_in[9];
    const float* fca_w     = (const float*)d_in[10];
    const float* fca_b     = (const float*)d_in[11];
    const float* fce_w     = (const float*)d_in[12];
    const float* fce_b     = (const float*)d_in[13];
    const float* vse_w1    = (const float*)d_in[14];
    const float* vse_b1    = (const float*)d_in[15];
    const float* vse_w2    = (const float*)d_in[16];
    const float* vse_b2    = (const float*)d_in[17];
    float* out = (float*)d_out;

    static bool attr_set = false;
    if (!attr_set) {
        cudaFuncSetAttribute(k_A, cudaFuncAttributeMaxDynamicSharedMemorySize, A_SMEM * 4);
        cudaFuncSetAttribute(k_B, cudaFuncAttributeMaxDynamicSharedMemorySize, B_SMEM * 4);
        attr_set = true;
    }

    k_h0<<<B_SZ, 512>>>(v, w2c_w1, w2c_b1);
    k_wcode<<<(6000 + 63) / 64, 256>>>(w2c_w2, w2c_b2);
    k_vs<<<1, 256>>>(vse_w1, vse_b1, vse_w2, vse_b2);
    k_A<<<(B_SZ * N_WRD) / 128, 512, A_SMEM * 4>>>(
        fc1_w, fc1_b, fc2_w, fc2_b, fca_w, fca_b, fce_w, fce_b);
    dim3 gridB((N_WRD + 127) / 128, B_SZ);
    k_B<<<gridB, 256, B_SMEM * 4>>>(view_cell, out);
}

// round 4
// speedup vs baseline: 2.3567x; 1.8454x over previous
#include <cuda_runtime.h>
#include <cstdint>

#define N_WRD  2000
#define B_SZ   64
#define CSZ    128
#define V_PIX  256
#define EMB    32

// ---------------- scratch (device globals; no allocations allowed) ----------
__device__ float    g_h0[B_SZ * 512];
__device__ float    g_wcode[B_SZ * 6000];
__device__ float    g_vs[V_PIX * EMB];
__device__ float    g_e[(size_t)B_SZ * N_WRD * EMB];
__device__ float    g_act[B_SZ * N_WRD];
__device__ uint32_t g_w2u[256 * 256];      // fc2_w as tf32 bits, [k][n]
__device__ uint32_t g_we2u[256 * 64];      // [fce|fca|0] as tf32 bits, [k][j]

// ============================ helpers =======================================
__device__ __forceinline__ uint32_t f2tf(float f) {
    uint32_t u; asm("cvt.rna.tf32.f32 %0, %1;" : "=r"(u) : "f"(f)); return u;
}
__device__ __forceinline__ void mma8(float* d, const uint32_t* a, const uint32_t* b) {
    asm volatile("mma.sync.aligned.m16n8k8.row.col.f32.tf32.tf32.f32 "
        "{%0,%1,%2,%3}, {%4,%5,%6,%7}, {%8,%9}, {%0,%1,%2,%3};"
        : "+f"(d[0]), "+f"(d[1]), "+f"(d[2]), "+f"(d[3])
        : "r"(a[0]), "r"(a[1]), "r"(a[2]), "r"(a[3]), "r"(b[0]), "r"(b[1]));
}
__device__ __forceinline__ float sigmoidf_(float x) {
    return 1.f / (1.f + __expf(-x));
}

// ---------------- kernel prep: tf32-convert weights -------------------------
__global__ void k_prep(const float* __restrict__ fc2_w,
                       const float* __restrict__ fce_w,
                       const float* __restrict__ fca_w) {
    int i = blockIdx.x * 256 + threadIdx.x;
    if (i < 65536) g_w2u[i] = f2tf(fc2_w[i]);
    if (i < 16384) {
        int k = i >> 6, j = i & 63;
        float v = 0.f;
        if (j < 32) v = fce_w[k * 32 + j];
        else if (j == 32) v = fca_w[k];
        g_we2u[i] = f2tf(v);
    }
}

// ---------------- kernel 1: h0 = relu(v @ w1 + b1) ---------------------------
__global__ void k_h0(const float* __restrict__ v,
                     const float* __restrict__ w1,
                     const float* __restrict__ b1) {
    int b = blockIdx.x;
    int j = threadIdx.x;
    float acc = b1[j];
#pragma unroll
    for (int i = 0; i < 7; i++) acc = fmaf(v[b * 7 + i], w1[i * 512 + j], acc);
    g_h0[b * 512 + j] = fmaxf(acc, 0.f);
}

// ---------------- kernel 2: wcode = h0 @ w2 + b2 ----------------------------
__global__ __launch_bounds__(256) void k_wcode(const float* __restrict__ w2,
                                               const float* __restrict__ b2) {
    __shared__ float As[64 * 33];
    __shared__ float Bs[32 * 68];
    int t = threadIdx.x;
    int tx = t & 15, ty = t >> 4;
    int n0 = blockIdx.x * 64;
    float acc[4][4] = {};
    for (int k0 = 0; k0 < 512; k0 += 32) {
        for (int i = t; i < 2048; i += 256) {
            int r = i >> 5, k = i & 31;
            As[r * 33 + k] = g_h0[r * 512 + k0 + k];
        }
        for (int i = t; i < 2048; i += 256) {
            int k = i >> 6, n = i & 63;
            int nn = n0 + n;
            Bs[k * 68 + n] = (nn < 6000) ? w2[(k0 + k) * 6000 + nn] : 0.f;
        }
        __syncthreads();
#pragma unroll
        for (int k = 0; k < 32; k++) {
            float a[4], bb[4];
#pragma unroll
            for (int i = 0; i < 4; i++) a[i] = As[(4 * ty + i) * 33 + k];
#pragma unroll
            for (int j = 0; j < 4; j++) bb[j] = Bs[k * 68 + 4 * tx + j];
#pragma unroll
            for (int i = 0; i < 4; i++)
#pragma unroll
                for (int j = 0; j < 4; j++) acc[i][j] = fmaf(a[i], bb[j], acc[i][j]);
        }
        __syncthreads();
    }
#pragma unroll
    for (int i = 0; i < 4; i++) {
        int r = 4 * ty + i;
#pragma unroll
        for (int j = 0; j < 4; j++) {
            int col = n0 + 4 * tx + j;
            if (col < 6000) g_wcode[r * 6000 + col] = acc[i][j] + b2[col];
        }
    }
}

// ---------------- kernel 3: vs ----------------------------------------------
__global__ void k_vs(const float* __restrict__ w1, const float* __restrict__ b1,
                     const float* __restrict__ w2, const float* __restrict__ b2) {
    int v = threadIdx.x;
    float x = -1.f + (2.f / 15.f) * (float)(v >> 4);
    float y = -1.f + (2.f / 15.f) * (float)(v & 15);
    float h[128];
#pragma unroll 4
    for (int j = 0; j < 128; j++)
        h[j] = fmaxf(fmaf(x, w1[j], fmaf(y, w1[128 + j], b1[j])), 0.f);
    for (int e = 0; e < EMB; e++) {
        float acc = b2[e];
#pragma unroll 4
        for (int j = 0; j < 128; j++) acc = fmaf(h[j], w2[j * EMB + e], acc);
        g_vs[v * EMB + e] = acc;
    }
}

// =============== kernel A (mma.sync tf32): fc1 -> fc2 -> fce/fca ============
// smem floats: As[128][260] @0 ; B2 region @33280 (Bs 32x260 / We2 256x68 /
//              e_stage 128x36) ; consts after.
#define KA_AS    0
#define KA_B2    33280
#define KA_FC2B  50688
#define KA_FCEB  50944
#define KA_F1W   50976
#define KA_F1B   51744
#define KA_WC    52000
#define KA_TOT   52384

__global__ __launch_bounds__(512, 1) void k_A(
    const float* __restrict__ fc1_w, const float* __restrict__ fc1_b,
    const float* __restrict__ fc2_b,
    const float* __restrict__ fca_b, const float* __restrict__ fce_b) {
    extern __shared__ float sm[];
    uint32_t* AsU  = (uint32_t*)(sm + KA_AS);
    uint32_t* B2U  = (uint32_t*)(sm + KA_B2);
    float*    B2F  = sm + KA_B2;
    float*    fc2bS= sm + KA_FC2B;
    float*    fcebS= sm + KA_FCEB;
    float*    f1w  = sm + KA_F1W;
    float*    f1b  = sm + KA_F1B;
    float*    wcS  = sm + KA_WC;

    const int t = threadIdx.x;
    const int wid = t >> 5, lane = t & 31;
    const int gr = lane >> 2, tg = lane & 3;
    const int row0 = blockIdx.x * 128;

    // stage constants
    for (int i = t; i < 768; i += 512) f1w[i] = fc1_w[i];
    if (t < 256) f1b[t] = fc1_b[t];
    if (t < 256) fc2bS[t] = fc2_b[t];
    if (t < 32) fcebS[t] = fce_b[t];
    for (int i = t; i < 384; i += 512) wcS[i] = g_wcode[row0 * 3 + i];
    __syncthreads();

    // ---- fc1 -> As (tf32 bits) ----
    {
        int r = t >> 2, kb = (t & 3) * 64;
        float w0 = wcS[r * 3 + 0], w1 = wcS[r * 3 + 1], w2 = wcS[r * 3 + 2];
        for (int j = 0; j < 64; j += 4) {
            uint4 u;
            int k = kb + j;
            u.x = f2tf(fmaxf(fmaf(w0, f1w[k+0], fmaf(w1, f1w[256+k+0], fmaf(w2, f1w[512+k+0], f1b[k+0]))), 0.f));
            u.y = f2tf(fmaxf(fmaf(w0, f1w[k+1], fmaf(w1, f1w[256+k+1], fmaf(w2, f1w[512+k+1], f1b[k+1]))), 0.f));
            u.z = f2tf(fmaxf(fmaf(w0, f1w[k+2], fmaf(w1, f1w[256+k+2], fmaf(w2, f1w[512+k+2], f1b[k+2]))), 0.f));
            u.w = f2tf(fmaxf(fmaf(w0, f1w[k+3], fmaf(w1, f1w[256+k+3], fmaf(w2, f1w[512+k+3], f1b[k+3]))), 0.f));
            *(uint4*)&AsU[r * 260 + k] = u;
        }
    }
    __syncthreads();

    // ---- MMA1: H2raw = A @ W2 (128x256, K=256), warps 4m x 4n, tile 32x64 --
    const int wm = wid & 3, wn = wid >> 2;
    const int m0 = wm * 32, n0 = wn * 64;
    float acc1[16][4] = {};
    for (int c = 0; c < 8; c++) {
        // stage Bs[32][260] <- g_w2u rows 32c..32c+31
        for (int i = t; i < 2048; i += 512) {
            int k = i >> 6, n4 = (i & 63) * 4;
            *(uint4*)&B2U[k * 260 + n4] = *(const uint4*)&g_w2u[(32 * c + k) * 256 + n4];
        }
        __syncthreads();
#pragma unroll
        for (int ks = 0; ks < 4; ks++) {
            int kk = ks * 8;
            int kb = 32 * c + kk;
            uint32_t a[2][4];
#pragma unroll
            for (int mt = 0; mt < 2; mt++) {
                int row = m0 + mt * 16 + gr;
                a[mt][0] = AsU[row * 260 + kb + tg];
                a[mt][1] = AsU[(row + 8) * 260 + kb + tg];
                a[mt][2] = AsU[row * 260 + kb + tg + 4];
                a[mt][3] = AsU[(row + 8) * 260 + kb + tg + 4];
            }
#pragma unroll
            for (int nt = 0; nt < 8; nt++) {
                int col = n0 + nt * 8 + gr;
                uint32_t b[2];
                b[0] = B2U[(kk + tg) * 260 + col];
                b[1] = B2U[(kk + tg + 4) * 260 + col];
#pragma unroll
                for (int mt = 0; mt < 2; mt++) mma8(acc1[mt * 8 + nt], a[mt], b);
            }
        }
        __syncthreads();
    }

    // ---- epilogue1: H2 = relu(acc+bias) -> As (tf32) ; stage We2 -----------
#pragma unroll
    for (int mt = 0; mt < 2; mt++) {
#pragma unroll
        for (int nt = 0; nt < 8; nt++) {
            int col = n0 + nt * 8 + 2 * tg;
            int r0 = m0 + mt * 16 + gr;
            float b0 = fc2bS[col], b1 = fc2bS[col + 1];
            float* d = acc1[mt * 8 + nt];
            uint2 u0, u1;
            u0.x = f2tf(fmaxf(d[0] + b0, 0.f));
            u0.y = f2tf(fmaxf(d[1] + b1, 0.f));
            u1.x = f2tf(fmaxf(d[2] + b0, 0.f));
            u1.y = f2tf(fmaxf(d[3] + b1, 0.f));
            *(uint2*)&AsU[r0 * 260 + col]       = u0;
            *(uint2*)&AsU[(r0 + 8) * 260 + col] = u1;
        }
    }
    // We2 [256][68]
    for (int i = t; i < 4096; i += 512) {
        int k = i >> 4, n4 = (i & 15) * 4;
        *(uint4*)&B2U[k * 68 + n4] = *(const uint4*)&g_we2u[k * 64 + n4];
    }
    __syncthreads();

    // ---- MMA2: D2 = H2 @ We2 (128x64, K=256), warps 4m x 4n, tile 32x16 ----
    const int n02 = wn * 16;
    float acc2[4][4] = {};
#pragma unroll 4
    for (int ks = 0; ks < 32; ks++) {
        int kb = ks * 8;
        uint32_t a[2][4];
#pragma unroll
        for (int mt = 0; mt < 2; mt++) {
            int row = m0 + mt * 16 + gr;
            a[mt][0] = AsU[row * 260 + kb + tg];
            a[mt][1] = AsU[(row + 8) * 260 + kb + tg];
            a[mt][2] = AsU[row * 260 + kb + tg + 4];
            a[mt][3] = AsU[(row + 8) * 260 + kb + tg + 4];
        }
#pragma unroll
        for (int nt = 0; nt < 2; nt++) {
            int col = n02 + nt * 8 + gr;
            uint32_t b[2];
            b[0] = B2U[(kb + tg) * 68 + col];
            b[1] = B2U[(kb + tg + 4) * 68 + col];
#pragma unroll
            for (int mt = 0; mt < 2; mt++) mma8(acc2[mt * 2 + nt], a[mt], b);
        }
    }
    __syncthreads();   // all We2 reads done; B2 region becomes e_stage

    // ---- epilogue2: e + act logit into e_stage [128][36] -------------------
    float* es = B2F;
#pragma unroll
    for (int mt = 0; mt < 2; mt++) {
#pragma unroll
        for (int nt = 0; nt < 2; nt++) {
            int col = n02 + nt * 8 + 2 * tg;
            int r0 = m0 + mt * 16 + gr;
            float* d = acc2[mt * 2 + nt];
            if (col < 32) {
                float b0 = fcebS[col], b1 = fcebS[col + 1];
                es[r0 * 36 + col]           = d[0] + b0;
                es[r0 * 36 + col + 1]       = d[1] + b1;
                es[(r0 + 8) * 36 + col]     = d[2] + b0;
                es[(r0 + 8) * 36 + col + 1] = d[3] + b1;
            } else if (col == 32) {
                es[r0 * 36 + 32]       = d[0];
                es[(r0 + 8) * 36 + 32] = d[2];
            }
        }
    }
    __syncthreads();
    for (int i = t; i < 1024; i += 512) {
        int r = i >> 3, j4 = (i & 7) * 4;
        float4 v = *(const float4*)&es[r * 36 + j4];
        *(float4*)&g_e[(size_t)(row0 + r) * 32 + j4] = v;
    }
    if (t < 128) g_act[row0 + t] = sigmoidf_(es[t * 36 + 32] + fca_b[0]);
}

// ======== kernel B: relation(mma) -> softmax -> route -> out GEMM(mma) ======
// smem floats:
#define KB_RT    0          // routeT [256][132] = 33792
#define KB_VST   33792      // vsT [32][260] = 8320 (tf32)
#define KB_ES    42112      // es  [128][36] = 4608 (tf32)
#define KB_AS2   46720      // VC chunk [128][36] = 4608 (tf32)
#define KB_ACT   51328      // 128
#define KB_RM    51456      // 128*17 = 2176
#define KB_RS    53632      // 2176
#define KB_TOT   55808

__global__ __launch_bounds__(512, 1) void k_B(const float* __restrict__ vc_g,
                                              float* __restrict__ out) {
    extern __shared__ float sm[];
    float*    rtF  = sm + KB_RT;
    uint32_t* rtU  = (uint32_t*)rtF;
    uint32_t* vsTU = (uint32_t*)(sm + KB_VST);
    uint32_t* esU  = (uint32_t*)(sm + KB_ES);
    uint32_t* as2U = (uint32_t*)(sm + KB_AS2);
    float*    actS = sm + KB_ACT;
    float*    redm = sm + KB_RM;
    float*    reds = sm + KB_RS;

    const int t = threadIdx.x;
    const int wid = t >> 5, lane = t & 31;
    const int gr = lane >> 2, tg = lane & 3;
    const int n0g = blockIdx.x * 128;
    const int b   = blockIdx.y;

    // stage vsT (tf32), es (tf32), act
    for (int i = t; i < 8192; i += 512) {
        int v = i >> 5, j = i & 31;
        vsTU[j * 260 + v] = f2tf(g_vs[i]);
    }
    for (int i = t; i < 4096; i += 512) {
        int n = i >> 5, j = i & 31;
        int row = n0g + n;
        float e = (row < N_WRD) ? g_e[(size_t)(b * N_WRD + row) * 32 + j] : 0.f;
        esU[n * 36 + j] = f2tf(e);
    }
    if (t < 128) {
        int row = n0g + t;
        actS[t] = (row < N_WRD) ? g_act[b * N_WRD + row] : 0.f;
    }
    __syncthreads();

    // ---- relation mma: (128n x 256v, K=32). warps 4m x 4v, tile 32x64 ------
    const int wm = wid & 3, wn = wid >> 2;
    const int m0 = wm * 32, v0 = wn * 64;
    {
        float accr[16][4] = {};
#pragma unroll
        for (int ks = 0; ks < 4; ks++) {
            int kb = ks * 8;
            uint32_t a[2][4];
#pragma unroll
            for (int mt = 0; mt < 2; mt++) {
                int row = m0 + mt * 16 + gr;
                a[mt][0] = esU[row * 36 + kb + tg];
                a[mt][1] = esU[(row + 8) * 36 + kb + tg];
                a[mt][2] = esU[row * 36 + kb + tg + 4];
                a[mt][3] = esU[(row + 8) * 36 + kb + tg + 4];
            }
#pragma unroll
            for (int nt = 0; nt < 8; nt++) {
                int col = v0 + nt * 8 + gr;
                uint32_t bb[2];
                bb[0] = vsTU[(kb + tg) * 260 + col];
                bb[1] = vsTU[(kb + tg + 4) * 260 + col];
#pragma unroll
                for (int mt = 0; mt < 2; mt++) mma8(accr[mt * 8 + nt], a[mt], bb);
            }
        }
        // scatter raw relation to routeT[v][n]
#pragma unroll
        for (int mt = 0; mt < 2; mt++) {
#pragma unroll
            for (int nt = 0; nt < 8; nt++) {
                int n = m0 + mt * 16 + gr;
                int v = v0 + nt * 8 + 2 * tg;
                float* d = accr[mt * 8 + nt];
                rtF[v * 132 + n]           = d[0];
                rtF[(v + 1) * 132 + n]     = d[1];
                rtF[v * 132 + n + 8]       = d[2];
                rtF[(v + 1) * 132 + n + 8] = d[3];
            }
        }
    }
    __syncthreads();

    // ---- softmax over v per n (16 warps, each owns 16 v-rows) --------------
    const int vb = wid * 16;
    for (int nc = 0; nc < 4; nc++) {
        int n = nc * 32 + lane;
        float mx = -1e30f;
#pragma unroll 4
        for (int vv = 0; vv < 16; vv++) mx = fmaxf(mx, rtF[(vb + vv) * 132 + n]);
        redm[n * 17 + wid] = mx;
    }
    __syncthreads();
    for (int nc = 0; nc < 4; nc++) {
        int n = nc * 32 + lane;
        float m = redm[n * 17];
#pragma unroll
        for (int i = 1; i < 16; i++) m = fmaxf(m, redm[n * 17 + i]);
        float s = 0.f;
#pragma unroll 4
        for (int vv = 0; vv < 16; vv++) {
            float x = __expf(rtF[(vb + vv) * 132 + n] - m);
            rtF[(vb + vv) * 132 + n] = x;
            s += x;
        }
        reds[n * 17 + wid] = s;
    }
    __syncthreads();
    for (int nc = 0; nc < 4; nc++) {
        int n = nc * 32 + lane;
        float s = 0.f;
#pragma unroll
        for (int i = 0; i < 16; i++) s += reds[n * 17 + i];
        float sc = actS[n] / s;
#pragma unroll 4
        for (int vv = 0; vv < 16; vv++)
            rtU[(vb + vv) * 132 + n] = f2tf(rtF[(vb + vv) * 132 + n] * sc);
    }

    // ---- output GEMM: out[c][n] = VC[c][v] @ route[v][n], K=256 ------------
    // warps 4m x 4n, tile 32x32
    const int n0 = wn * 32;
    float acco[8][4] = {};
    const float* A = vc_g + (size_t)b * CSZ * V_PIX;
    for (int c = 0; c < 8; c++) {
        __syncthreads();
        for (int i = t; i < 1024; i += 512) {
            int r = i >> 3, k4 = (i & 7) * 4;
            float4 v = *(const float4*)&A[r * 256 + 32 * c + k4];
            uint4 u;
            u.x = f2tf(v.x); u.y = f2tf(v.y); u.z = f2tf(v.z); u.w = f2tf(v.w);
            *(uint4*)&as2U[r * 36 + k4] = u;
        }
        __syncthreads();
#pragma unroll
        for (int ks = 0; ks < 4; ks++) {
            int kk = ks * 8;
            uint32_t a[2][4];
#pragma unroll
            for (int mt = 0; mt < 2; mt++) {
                int row = m0 + mt * 16 + gr;
                a[mt][0] = as2U[row * 36 + kk + tg];
                a[mt][1] = as2U[(row + 8) * 36 + kk + tg];
                a[mt][2] = as2U[row * 36 + kk + tg + 4];
                a[mt][3] = as2U[(row + 8) * 36 + kk + tg + 4];
            }
#pragma unroll
            for (int nt = 0; nt < 4; nt++) {
                int col = n0 + nt * 8 + gr;
                uint32_t bb[2];
                bb[0] = rtU[(32 * c + kk + tg) * 132 + col];
                bb[1] = rtU[(32 * c + kk + tg + 4) * 132 + col];
#pragma unroll
                for (int mt = 0; mt < 2; mt++) mma8(acco[mt * 4 + nt], a[mt], bb);
            }
        }
    }
    // store
#pragma unroll
    for (int mt = 0; mt < 2; mt++) {
#pragma unroll
        for (int nt = 0; nt < 4; nt++) {
            int r0 = m0 + mt * 16 + gr;
            int ng = n0g + n0 + nt * 8 + 2 * tg;
            float* d = acco[mt * 4 + nt];
            if (ng < N_WRD) {
                float2 s0; s0.x = d[0]; s0.y = d[1];
                float2 s1; s1.x = d[2]; s1.y = d[3];
                *(float2*)&out[((size_t)b * CSZ + r0) * N_WRD + ng]     = s0;
                *(float2*)&out[((size_t)b * CSZ + r0 + 8) * N_WRD + ng] = s1;
            }
        }
    }
}

// ---------------- launch --------------------------------------------------
extern "C" void kernel_launch(void* const* d_in, const int* in_sizes, int n_in,
                              void* d_out, int out_size) {
    const float* view_cell = (const float*)d_in[0];
    const float* v         = (const float*)d_in[1];
    const float* w2c_w1    = (const float*)d_in[2];
    const float* w2c_b1    = (const float*)d_in[3];
    const float* w2c_w2    = (const float*)d_in[4];
    const float* w2c_b2    = (const float*)d_in[5];
    const float* fc1_w     = (const float*)d_in[6];
    const float* fc1_b     = (const float*)d_in[7];
    const float* fc2_w     = (const float*)d_in[8];
    const float* fc2_b     = (const float*)d_in[9];
    const float* fca_w     = (const float*)d_in[10];
    const float* fca_b     = (const float*)d_in[11];
    const float* fce_w     = (const float*)d_in[12];
    const float* fce_b     = (const float*)d_in[13];
    const float* vse_w1    = (const float*)d_in[14];
    const float* vse_b1    = (const float*)d_in[15];
    const float* vse_w2    = (const float*)d_in[16];
    const float* vse_b2    = (const float*)d_in[17];
    float* out = (float*)d_out;

    static bool attr_set = false;
    if (!attr_set) {
        cudaFuncSetAttribute(k_A, cudaFuncAttributeMaxDynamicSharedMemorySize, KA_TOT * 4);
        cudaFuncSetAttribute(k_B, cudaFuncAttributeMaxDynamicSharedMemorySize, KB_TOT * 4);
        attr_set = true;
    }

    k_prep<<<256, 256>>>(fc2_w, fce_w, fca_w);
    k_h0<<<B_SZ, 512>>>(v, w2c_w1, w2c_b1);
    k_wcode<<<(6000 + 63) / 64, 256>>>(w2c_w2, w2c_b2);
    k_vs<<<1, 256>>>(vse_w1, vse_b1, vse_w2, vse_b2);
    k_A<<<(B_SZ * N_WRD) / 128, 512, KA_TOT * 4>>>(fc1_w, fc1_b, fc2_b, fca_b, fce_b);
    dim3 gridB((N_WRD + 127) / 128, B_SZ);
    k_B<<<gridB, 512, KB_TOT * 4>>>(view_cell, out);
}

// round 5
// speedup vs baseline: 2.9613x; 1.2565x over previous
#include <cuda_runtime.h>
#include <cstdint>

#define N_WRD  2000
#define B_SZ   64
#define CSZ    128
#define V_PIX  256
#define EMB    32

// ---------------- scratch (device globals; no allocations allowed) ----------
__device__ float    g_h0[B_SZ * 512];
__device__ float    g_wcode[B_SZ * 6000];
__device__ float    g_vs[V_PIX * EMB];
__device__ float    g_e[(size_t)B_SZ * N_WRD * EMB];
__device__ float    g_act[B_SZ * N_WRD];
__device__ uint32_t g_w2u[256 * 256];      // fc2_w as tf32 bits, [k][n]
__device__ uint32_t g_we2u[256 * 64];      // [fce|fca|0] as tf32 bits, [k][j]

// ============================ helpers =======================================
__device__ __forceinline__ uint32_t f2tf(float f) {
    uint32_t u; asm("cvt.rna.tf32.f32 %0, %1;" : "=r"(u) : "f"(f)); return u;
}
__device__ __forceinline__ void mma8(float* d, const uint32_t* a, const uint32_t* b) {
    asm volatile("mma.sync.aligned.m16n8k8.row.col.f32.tf32.tf32.f32 "
        "{%0,%1,%2,%3}, {%4,%5,%6,%7}, {%8,%9}, {%0,%1,%2,%3};"
        : "+f"(d[0]), "+f"(d[1]), "+f"(d[2]), "+f"(d[3])
        : "r"(a[0]), "r"(a[1]), "r"(a[2]), "r"(a[3]), "r"(b[0]), "r"(b[1]));
}
__device__ __forceinline__ float sigmoidf_(float x) {
    return 1.f / (1.f + __expf(-x));
}

// ====== setup kernel: prep (tf32 weights) + h0 + vs, role-split blocks ======
__global__ __launch_bounds__(256) void k_setup(
    const float* __restrict__ fc2_w, const float* __restrict__ fce_w,
    const float* __restrict__ fca_w,
    const float* __restrict__ v, const float* __restrict__ w2c_w1,
    const float* __restrict__ w2c_b1,
    const float* __restrict__ vse_w1, const float* __restrict__ vse_b1,
    const float* __restrict__ vse_w2, const float* __restrict__ vse_b2) {
    const int bid = blockIdx.x;
    const int t = threadIdx.x;
    if (bid < 256) {
        // prep: 65536 fc2 conversions (1 each) + 16384 we2 (blocks 0-63)
        int i = bid * 256 + t;
        g_w2u[i] = f2tf(fc2_w[i]);
        if (i < 16384) {
            int k = i >> 6, j = i & 63;
            float val = 0.f;
            if (j < 32) val = fce_w[k * 32 + j];
            else if (j == 32) val = fca_w[k];
            g_we2u[i] = f2tf(val);
        }
    } else if (bid < 320) {
        // h0: b = bid-256, threads cover j and j+256
        int b = bid - 256;
#pragma unroll
        for (int half = 0; half < 2; half++) {
            int j = t + half * 256;
            float acc = w2c_b1[j];
#pragma unroll
            for (int i = 0; i < 7; i++)
                acc = fmaf(v[b * 7 + i], w2c_w1[i * 512 + j], acc);
            g_h0[b * 512 + j] = fmaxf(acc, 0.f);
        }
    } else {
        // vs: 32 blocks, thread = (v_local 0..7, e 0..31)
        int vl = t >> 5, e = t & 31;
        int vv = (bid - 320) * 8 + vl;
        float x = -1.f + (2.f / 15.f) * (float)(vv >> 4);
        float y = -1.f + (2.f / 15.f) * (float)(vv & 15);
        float acc = vse_b2[e];
#pragma unroll 4
        for (int j = 0; j < 128; j++) {
            float h = fmaxf(fmaf(x, vse_w1[j], fmaf(y, vse_w1[128 + j], vse_b1[j])), 0.f);
            acc = fmaf(h, vse_w2[j * EMB + e], acc);
        }
        g_vs[vv * EMB + e] = acc;
    }
}

// ---------------- kernel 2: wcode = h0 @ w2 + b2 ----------------------------
__global__ __launch_bounds__(256) void k_wcode(const float* __restrict__ w2,
                                               const float* __restrict__ b2) {
    __shared__ float As[64 * 33];
    __shared__ float Bs[32 * 68];
    int t = threadIdx.x;
    int tx = t & 15, ty = t >> 4;
    int n0 = blockIdx.x * 64;
    float acc[4][4] = {};
    for (int k0 = 0; k0 < 512; k0 += 32) {
        for (int i = t; i < 2048; i += 256) {
            int r = i >> 5, k = i & 31;
            As[r * 33 + k] = g_h0[r * 512 + k0 + k];
        }
        for (int i = t; i < 2048; i += 256) {
            int k = i >> 6, n = i & 63;
            int nn = n0 + n;
            Bs[k * 68 + n] = (nn < 6000) ? w2[(k0 + k) * 6000 + nn] : 0.f;
        }
        __syncthreads();
#pragma unroll
        for (int k = 0; k < 32; k++) {
            float a[4], bb[4];
#pragma unroll
            for (int i = 0; i < 4; i++) a[i] = As[(4 * ty + i) * 33 + k];
#pragma unroll
            for (int j = 0; j < 4; j++) bb[j] = Bs[k * 68 + 4 * tx + j];
#pragma unroll
            for (int i = 0; i < 4; i++)
#pragma unroll
                for (int j = 0; j < 4; j++) acc[i][j] = fmaf(a[i], bb[j], acc[i][j]);
        }
        __syncthreads();
    }
#pragma unroll
    for (int i = 0; i < 4; i++) {
        int r = 4 * ty + i;
#pragma unroll
        for (int j = 0; j < 4; j++) {
            int col = n0 + 4 * tx + j;
            if (col < 6000) g_wcode[r * 6000 + col] = acc[i][j] + b2[col];
        }
    }
}

// =============== kernel A (mma.sync tf32): fc1 -> fc2 -> fce/fca ============
#define KA_AS    0
#define KA_B2    33280
#define KA_FC2B  50688
#define KA_FCEB  50944
#define KA_F1W   50976
#define KA_F1B   51744
#define KA_WC    52000
#define KA_TOT   52384

__global__ __launch_bounds__(512, 1) void k_A(
    const float* __restrict__ fc1_w, const float* __restrict__ fc1_b,
    const float* __restrict__ fc2_b,
    const float* __restrict__ fca_b, const float* __restrict__ fce_b) {
    extern __shared__ float sm[];
    uint32_t* AsU  = (uint32_t*)(sm + KA_AS);
    uint32_t* B2U  = (uint32_t*)(sm + KA_B2);
    float*    B2F  = sm + KA_B2;
    float*    fc2bS= sm + KA_FC2B;
    float*    fcebS= sm + KA_FCEB;
    float*    f1w  = sm + KA_F1W;
    float*    f1b  = sm + KA_F1B;
    float*    wcS  = sm + KA_WC;

    const int t = threadIdx.x;
    const int wid = t >> 5, lane = t & 31;
    const int gr = lane >> 2, tg = lane & 3;
    const int row0 = blockIdx.x * 128;

    for (int i = t; i < 768; i += 512) f1w[i] = fc1_w[i];
    if (t < 256) f1b[t] = fc1_b[t];
    if (t < 256) fc2bS[t] = fc2_b[t];
    if (t < 32) fcebS[t] = fce_b[t];
    for (int i = t; i < 384; i += 512) wcS[i] = g_wcode[row0 * 3 + i];
    __syncthreads();

    // ---- fc1 -> As (tf32 bits) ----
    {
        int r = t >> 2, kb = (t & 3) * 64;
        float w0 = wcS[r * 3 + 0], w1 = wcS[r * 3 + 1], w2 = wcS[r * 3 + 2];
        for (int j = 0; j < 64; j += 4) {
            uint4 u;
            int k = kb + j;
            u.x = f2tf(fmaxf(fmaf(w0, f1w[k+0], fmaf(w1, f1w[256+k+0], fmaf(w2, f1w[512+k+0], f1b[k+0]))), 0.f));
            u.y = f2tf(fmaxf(fmaf(w0, f1w[k+1], fmaf(w1, f1w[256+k+1], fmaf(w2, f1w[512+k+1], f1b[k+1]))), 0.f));
            u.z = f2tf(fmaxf(fmaf(w0, f1w[k+2], fmaf(w1, f1w[256+k+2], fmaf(w2, f1w[512+k+2], f1b[k+2]))), 0.f));
            u.w = f2tf(fmaxf(fmaf(w0, f1w[k+3], fmaf(w1, f1w[256+k+3], fmaf(w2, f1w[512+k+3], f1b[k+3]))), 0.f));
            *(uint4*)&AsU[r * 260 + k] = u;
        }
    }

    // prologue: stage W2 chunk 0
    {
        int i = t;
        int k = i >> 6, n4 = (i & 63) * 4;
        uint4 q0 = *(const uint4*)&g_w2u[k * 256 + n4];
        uint4 q1 = *(const uint4*)&g_w2u[(k + 8) * 256 + n4];
        uint4 q2 = *(const uint4*)&g_w2u[(k + 16) * 256 + n4];
        uint4 q3 = *(const uint4*)&g_w2u[(k + 24) * 256 + n4];
        __syncthreads();   // fc1 writes + staging reads ordered
        *(uint4*)&B2U[k * 260 + n4]        = q0;
        *(uint4*)&B2U[(k + 8) * 260 + n4]  = q1;
        *(uint4*)&B2U[(k + 16) * 260 + n4] = q2;
        *(uint4*)&B2U[(k + 24) * 260 + n4] = q3;
    }
    __syncthreads();

    // ---- MMA1: H2raw = A @ W2 (128x256, K=256), warps 4m x 4n, tile 32x64 --
    const int wm = wid & 3, wn = wid >> 2;
    const int m0 = wm * 32, n0 = wn * 64;
    float acc1[16][4] = {};
    for (int c = 0; c < 8; c++) {
        uint4 pf[4];
        if (c < 7) {
            int k = t >> 6, n4 = (t & 63) * 4;
#pragma unroll
            for (int q = 0; q < 4; q++)
                pf[q] = *(const uint4*)&g_w2u[(32 * (c + 1) + k + 8 * q) * 256 + n4];
        }
#pragma unroll
        for (int ks = 0; ks < 4; ks++) {
            int kk = ks * 8;
            int kb = 32 * c + kk;
            uint32_t a[2][4];
#pragma unroll
            for (int mt = 0; mt < 2; mt++) {
                int row = m0 + mt * 16 + gr;
                a[mt][0] = AsU[row * 260 + kb + tg];
                a[mt][1] = AsU[(row + 8) * 260 + kb + tg];
                a[mt][2] = AsU[row * 260 + kb + tg + 4];
                a[mt][3] = AsU[(row + 8) * 260 + kb + tg + 4];
            }
#pragma unroll
            for (int nt = 0; nt < 8; nt++) {
                int col = n0 + nt * 8 + gr;
                uint32_t b[2];
                b[0] = B2U[(kk + tg) * 260 + col];
                b[1] = B2U[(kk + tg + 4) * 260 + col];
#pragma unroll
                for (int mt = 0; mt < 2; mt++) mma8(acc1[mt * 8 + nt], a[mt], b);
            }
        }
        __syncthreads();
        if (c < 7) {
            int k = t >> 6, n4 = (t & 63) * 4;
#pragma unroll
            for (int q = 0; q < 4; q++)
                *(uint4*)&B2U[(k + 8 * q) * 260 + n4] = pf[q];
            __syncthreads();
        }
    }

    // ---- epilogue1: H2 = relu(acc+bias) -> As (tf32) ; stage We2 -----------
#pragma unroll
    for (int mt = 0; mt < 2; mt++) {
#pragma unroll
        for (int nt = 0; nt < 8; nt++) {
            int col = n0 + nt * 8 + 2 * tg;
            int r0 = m0 + mt * 16 + gr;
            float b0 = fc2bS[col], b1 = fc2bS[col + 1];
            float* d = acc1[mt * 8 + nt];
            uint2 u0, u1;
            u0.x = f2tf(fmaxf(d[0] + b0, 0.f));
            u0.y = f2tf(fmaxf(d[1] + b1, 0.f));
            u1.x = f2tf(fmaxf(d[2] + b0, 0.f));
            u1.y = f2tf(fmaxf(d[3] + b1, 0.f));
            *(uint2*)&AsU[r0 * 260 + col]       = u0;
            *(uint2*)&AsU[(r0 + 8) * 260 + col] = u1;
        }
    }
    for (int i = t; i < 4096; i += 512) {
        int k = i >> 4, n4 = (i & 15) * 4;
        *(uint4*)&B2U[k * 68 + n4] = *(const uint4*)&g_we2u[k * 64 + n4];
    }
    __syncthreads();

    // ---- MMA2: D2 = H2 @ We2 (128x64, K=256), warps 4m x 4n, tile 32x16 ----
    const int n02 = wn * 16;
    float acc2[4][4] = {};
#pragma unroll 4
    for (int ks = 0; ks < 32; ks++) {
        int kb = ks * 8;
        uint32_t a[2][4];
#pragma unroll
        for (int mt = 0; mt < 2; mt++) {
            int row = m0 + mt * 16 + gr;
            a[mt][0] = AsU[row * 260 + kb + tg];
            a[mt][1] = AsU[(row + 8) * 260 + kb + tg];
            a[mt][2] = AsU[row * 260 + kb + tg + 4];
            a[mt][3] = AsU[(row + 8) * 260 + kb + tg + 4];
        }
#pragma unroll
        for (int nt = 0; nt < 2; nt++) {
            int col = n02 + nt * 8 + gr;
            uint32_t b[2];
            b[0] = B2U[(kb + tg) * 68 + col];
            b[1] = B2U[(kb + tg + 4) * 68 + col];
#pragma unroll
            for (int mt = 0; mt < 2; mt++) mma8(acc2[mt * 2 + nt], a[mt], b);
        }
    }
    __syncthreads();

    // ---- epilogue2: e + act logit into e_stage [128][36] -------------------
    float* es = B2F;
#pragma unroll
    for (int mt = 0; mt < 2; mt++) {
#pragma unroll
        for (int nt = 0; nt < 2; nt++) {
            int col = n02 + nt * 8 + 2 * tg;
            int r0 = m0 + mt * 16 + gr;
            float* d = acc2[mt * 2 + nt];
            if (col < 32) {
                float b0 = fcebS[col], b1 = fcebS[col + 1];
                es[r0 * 36 + col]           = d[0] + b0;
                es[r0 * 36 + col + 1]       = d[1] + b1;
                es[(r0 + 8) * 36 + col]     = d[2] + b0;
                es[(r0 + 8) * 36 + col + 1] = d[3] + b1;
            } else if (col == 32) {
                es[r0 * 36 + 32]       = d[0];
                es[(r0 + 8) * 36 + 32] = d[2];
            }
        }
    }
    __syncthreads();
    for (int i = t; i < 1024; i += 512) {
        int r = i >> 3, j4 = (i & 7) * 4;
        float4 vv = *(const float4*)&es[r * 36 + j4];
        *(float4*)&g_e[(size_t)(row0 + r) * 32 + j4] = vv;
    }
    if (t < 128) g_act[row0 + t] = sigmoidf_(es[t * 36 + 32] + fca_b[0]);
}

// ======== kernel B: relation(mma) -> softmax -> route -> out GEMM(mma) ======
#define KB_RT    0          // routeT [256][132] = 33792
#define KB_VST   33792      // vsT [32][260] = 8320 (tf32)
#define KB_ES    42112      // es  [128][36] = 4608 (tf32)
#define KB_AS2   46720      // VC chunk [128][36] = 4608 (tf32)
#define KB_ACT   51328      // 128
#define KB_RM    51456      // 128*17 = 2176
#define KB_RS    53632      // 2176
#define KB_TOT   55808

__global__ __launch_bounds__(512, 1) void k_B(const float* __restrict__ vc_g,
                                              float* __restrict__ out) {
    extern __shared__ float sm[];
    float*    rtF  = sm + KB_RT;
    uint32_t* rtU  = (uint32_t*)rtF;
    uint32_t* vsTU = (uint32_t*)(sm + KB_VST);
    uint32_t* esU  = (uint32_t*)(sm + KB_ES);
    uint32_t* as2U = (uint32_t*)(sm + KB_AS2);
    float*    actS = sm + KB_ACT;
    float*    redm = sm + KB_RM;
    float*    reds = sm + KB_RS;

    const int t = threadIdx.x;
    const int wid = t >> 5, lane = t & 31;
    const int gr = lane >> 2, tg = lane & 3;
    const int n0g = blockIdx.x * 128;
    const int b   = blockIdx.y;

    for (int i = t; i < 8192; i += 512) {
        int v = i >> 5, j = i & 31;
        vsTU[j * 260 + v] = f2tf(g_vs[i]);
    }
    for (int i = t; i < 4096; i += 512) {
        int n = i >> 5, j = i & 31;
        int row = n0g + n;
        float e = (row < N_WRD) ? g_e[(size_t)(b * N_WRD + row) * 32 + j] : 0.f;
        esU[n * 36 + j] = f2tf(e);
    }
    if (t < 128) {
        int row = n0g + t;
        actS[t] = (row < N_WRD) ? g_act[b * N_WRD + row] : 0.f;
    }
    __syncthreads();

    const int wm = wid & 3, wn = wid >> 2;
    const int m0 = wm * 32, v0 = wn * 64;
    {
        float accr[16][4] = {};
#pragma unroll
        for (int ks = 0; ks < 4; ks++) {
            int kb = ks * 8;
            uint32_t a[2][4];
#pragma unroll
            for (int mt = 0; mt < 2; mt++) {
                int row = m0 + mt * 16 + gr;
                a[mt][0] = esU[row * 36 + kb + tg];
                a[mt][1] = esU[(row + 8) * 36 + kb + tg];
                a[mt][2] = esU[row * 36 + kb + tg + 4];
                a[mt][3] = esU[(row + 8) * 36 + kb + tg + 4];
            }
#pragma unroll
            for (int nt = 0; nt < 8; nt++) {
                int col = v0 + nt * 8 + gr;
                uint32_t bb[2];
                bb[0] = vsTU[(kb + tg) * 260 + col];
                bb[1] = vsTU[(kb + tg + 4) * 260 + col];
#pragma unroll
                for (int mt = 0; mt < 2; mt++) mma8(accr[mt * 8 + nt], a[mt], bb);
            }
        }
#pragma unroll
        for (int mt = 0; mt < 2; mt++) {
#pragma unroll
            for (int nt = 0; nt < 8; nt++) {
                int n = m0 + mt * 16 + gr;
                int v = v0 + nt * 8 + 2 * tg;
                float* d = accr[mt * 8 + nt];
                rtF[v * 132 + n]           = d[0];
                rtF[(v + 1) * 132 + n]     = d[1];
                rtF[v * 132 + n + 8]       = d[2];
                rtF[(v + 1) * 132 + n + 8] = d[3];
            }
        }
    }
    __syncthreads();

    const int vb = wid * 16;
    for (int nc = 0; nc < 4; nc++) {
        int n = nc * 32 + lane;
        float mx = -1e30f;
#pragma unroll 4
        for (int vv = 0; vv < 16; vv++) mx = fmaxf(mx, rtF[(vb + vv) * 132 + n]);
        redm[n * 17 + wid] = mx;
    }
    __syncthreads();
    for (int nc = 0; nc < 4; nc++) {
        int n = nc * 32 + lane;
        float m = redm[n * 17];
#pragma unroll
        for (int i = 1; i < 16; i++) m = fmaxf(m, redm[n * 17 + i]);
        float s = 0.f;
#pragma unroll 4
        for (int vv = 0; vv < 16; vv++) {
            float x = __expf(rtF[(vb + vv) * 132 + n] - m);
            rtF[(vb + vv) * 132 + n] = x;
            s += x;
        }
        reds[n * 17 + wid] = s;
    }
    __syncthreads();
    for (int nc = 0; nc < 4; nc++) {
        int n = nc * 32 + lane;
        float s = 0.f;
#pragma unroll
        for (int i = 0; i < 16; i++) s += reds[n * 17 + i];
        float sc = actS[n] / s;
#pragma unroll 4
        for (int vv = 0; vv < 16; vv++)
            rtU[(vb + vv) * 132 + n] = f2tf(rtF[(vb + vv) * 132 + n] * sc);
    }

    const int n0 = wn * 32;
    float acco[8][4] = {};
    const float* A = vc_g + (size_t)b * CSZ * V_PIX;
    for (int c = 0; c < 8; c++) {
        __syncthreads();
        for (int i = t; i < 1024; i += 512) {
            int r = i >> 3, k4 = (i & 7) * 4;
            float4 vv = *(const float4*)&A[r * 256 + 32 * c + k4];
            uint4 u;
            u.x = f2tf(vv.x); u.y = f2tf(vv.y); u.z = f2tf(vv.z); u.w = f2tf(vv.w);
            *(uint4*)&as2U[r * 36 + k4] = u;
        }
        __syncthreads();
#pragma unroll
        for (int ks = 0; ks < 4; ks++) {
            int kk = ks * 8;
            uint32_t a[2][4];
#pragma unroll
            for (int mt = 0; mt < 2; mt++) {
                int row = m0 + mt * 16 + gr;
                a[mt][0] = as2U[row * 36 + kk + tg];
                a[mt][1] = as2U[(row + 8) * 36 + kk + tg];
                a[mt][2] = as2U[row * 36 + kk + tg + 4];
                a[mt][3] = as2U[(row + 8) * 36 + kk + tg + 4];
            }
#pragma unroll
            for (int nt = 0; nt < 4; nt++) {
                int col = n0 + nt * 8 + gr;
                uint32_t bb[2];
                bb[0] = rtU[(32 * c + kk + tg) * 132 + col];
                bb[1] = rtU[(32 * c + kk + tg + 4) * 132 + col];
#pragma unroll
                for (int mt = 0; mt < 2; mt++) mma8(acco[mt * 4 + nt], a[mt], bb);
            }
        }
    }
#pragma unroll
    for (int mt = 0; mt < 2; mt++) {
#pragma unroll
        for (int nt = 0; nt < 4; nt++) {
            int r0 = m0 + mt * 16 + gr;
            int ng = n0g + n0 + nt * 8 + 2 * tg;
            float* d = acco[mt * 4 + nt];
            if (ng < N_WRD) {
                float2 s0; s0.x = d[0]; s0.y = d[1];
                float2 s1; s1.x = d[2]; s1.y = d[3];
                *(float2*)&out[((size_t)b * CSZ + r0) * N_WRD + ng]     = s0;
                *(float2*)&out[((size_t)b * CSZ + r0 + 8) * N_WRD + ng] = s1;
            }
        }
    }
}

// ---------------- launch --------------------------------------------------
extern "C" void kernel_launch(void* const* d_in, const int* in_sizes, int n_in,
                              void* d_out, int out_size) {
    const float* view_cell = (const float*)d_in[0];
    const float* v         = (const float*)d_in[1];
    const float* w2c_w1    = (const float*)d_in[2];
    const float* w2c_b1    = (const float*)d_in[3];
    const float* w2c_w2    = (const float*)d_in[4];
    const float* w2c_b2    = (const float*)d_in[5];
    const float* fc1_w     = (const float*)d_in[6];
    const float* fc1_b     = (const float*)d_in[7];
    const float* fc2_w     = (const float*)d_in[8];
    const float* fc2_b     = (const float*)d_in[9];
    const float* fca_w     = (const float*)d_in[10];
    const float* fca_b     = (const float*)d_in[11];
    const float* fce_w     = (const float*)d_in[12];
    const float* fce_b     = (const float*)d_in[13];
    const float* vse_w1    = (const float*)d_in[14];
    const float* vse_b1    = (const float*)d_in[15];
    const float* vse_w2    = (const float*)d_in[16];
    const float* vse_b2    = (const float*)d_in[17];
    float* out = (float*)d_out;

    static bool attr_set = false;
    if (!attr_set) {
        cudaFuncSetAttribute(k_A, cudaFuncAttributeMaxDynamicSharedMemorySize, KA_TOT * 4);
        cudaFuncSetAttribute(k_B, cudaFuncAttributeMaxDynamicSharedMemorySize, KB_TOT * 4);
        attr_set = true;
    }

    k_setup<<<352, 256>>>(fc2_w, fce_w, fca_w, v, w2c_w1, w2c_b1,
                          vse_w1, vse_b1, vse_w2, vse_b2);
    k_wcode<<<(6000 + 63) / 64, 256>>>(w2c_w2, w2c_b2);
    k_A<<<(B_SZ * N_WRD) / 128, 512, KA_TOT * 4>>>(fc1_w, fc1_b, fc2_b, fca_b, fce_b);
    dim3 gridB((N_WRD + 127) / 128, B_SZ);
    k_B<<<gridB, 512, KB_TOT * 4>>>(view_cell, out);
}

// round 6
// speedup vs baseline: 3.6635x; 1.2371x over previous
#include <cuda_runtime.h>
#include <cstdint>

#define N_WRD  2000
#define B_SZ   64
#define CSZ    128
#define V_PIX  256
#define EMB    32

// ---------------- scratch (device globals; no allocations allowed) ----------
__device__ float    g_h0[B_SZ * 512];
__device__ float    g_wcode[B_SZ * 6000];
__device__ float    g_vs[V_PIX * EMB];
__device__ float    g_e[(size_t)B_SZ * N_WRD * EMB];
__device__ float    g_act[B_SZ * N_WRD];
__device__ uint32_t g_w2u[256 * 256];      // fc2_w as tf32 bits, [k][n]
__device__ uint32_t g_we2u[256 * 64];      // [fce|fca|0] as tf32 bits, [k][j]

// ============================ helpers =======================================
__device__ __forceinline__ uint32_t f2tf(float f) {
    uint32_t u; asm("cvt.rna.tf32.f32 %0, %1;" : "=r"(u) : "f"(f)); return u;
}
__device__ __forceinline__ void mma8(float* d, const uint32_t* a, const uint32_t* b) {
    asm volatile("mma.sync.aligned.m16n8k8.row.col.f32.tf32.tf32.f32 "
        "{%0,%1,%2,%3}, {%4,%5,%6,%7}, {%8,%9}, {%0,%1,%2,%3};"
        : "+f"(d[0]), "+f"(d[1]), "+f"(d[2]), "+f"(d[3])
        : "r"(a[0]), "r"(a[1]), "r"(a[2]), "r"(a[3]), "r"(b[0]), "r"(b[1]));
}
__device__ __forceinline__ void ldm_x4(uint32_t* r, uint32_t addr) {
    asm volatile("ldmatrix.sync.aligned.m8n8.x4.shared.b16 {%0,%1,%2,%3}, [%4];"
        : "=r"(r[0]), "=r"(r[1]), "=r"(r[2]), "=r"(r[3]) : "r"(addr));
}
__device__ __forceinline__ uint32_t smem_u32(const void* p) {
    uint32_t a;
    asm("{ .reg .u64 t; cvta.to.shared.u64 t, %1; cvt.u32.u64 %0, t; }"
        : "=r"(a) : "l"(p));
    return a;
}
#define CP_ASYNC16(dst, src) \
    asm volatile("cp.async.ca.shared.global [%0], [%1], 16;" :: "r"(dst), "l"(src))
#define CP_COMMIT() asm volatile("cp.async.commit_group;")
#define CP_WAIT1()  asm volatile("cp.async.wait_group 1;")
#define CP_WAIT0()  asm volatile("cp.async.wait_group 0;")
__device__ __forceinline__ float sigmoidf_(float x) {
    return 1.f / (1.f + __expf(-x));
}

// ====== setup kernel: prep (tf32 weights) + h0 + vs, role-split blocks ======
__global__ __launch_bounds__(256) void k_setup(
    const float* __restrict__ fc2_w, const float* __restrict__ fce_w,
    const float* __restrict__ fca_w,
    const float* __restrict__ v, const float* __restrict__ w2c_w1,
    const float* __restrict__ w2c_b1,
    const float* __restrict__ vse_w1, const float* __restrict__ vse_b1,
    const float* __restrict__ vse_w2, const float* __restrict__ vse_b2) {
    const int bid = blockIdx.x;
    const int t = threadIdx.x;
    if (bid < 256) {
        int i = bid * 256 + t;
        g_w2u[i] = f2tf(fc2_w[i]);
        if (i < 16384) {
            int k = i >> 6, j = i & 63;
            float val = 0.f;
            if (j < 32) val = fce_w[k * 32 + j];
            else if (j == 32) val = fca_w[k];
            g_we2u[i] = f2tf(val);
        }
    } else if (bid < 320) {
        int b = bid - 256;
#pragma unroll
        for (int half = 0; half < 2; half++) {
            int j = t + half * 256;
            float acc = w2c_b1[j];
#pragma unroll
            for (int i = 0; i < 7; i++)
                acc = fmaf(v[b * 7 + i], w2c_w1[i * 512 + j], acc);
            g_h0[b * 512 + j] = fmaxf(acc, 0.f);
        }
    } else {
        int vl = t >> 5, e = t & 31;
        int vv = (bid - 320) * 8 + vl;
        float x = -1.f + (2.f / 15.f) * (float)(vv >> 4);
        float y = -1.f + (2.f / 15.f) * (float)(vv & 15);
        float acc = vse_b2[e];
#pragma unroll 4
        for (int j = 0; j < 128; j++) {
            float h = fmaxf(fmaf(x, vse_w1[j], fmaf(y, vse_w1[128 + j], vse_b1[j])), 0.f);
            acc = fmaf(h, vse_w2[j * EMB + e], acc);
        }
        g_vs[vv * EMB + e] = acc;
    }
}

// ---------------- kernel 2: wcode = h0 @ w2 + b2 ----------------------------
__global__ __launch_bounds__(256) void k_wcode(const float* __restrict__ w2,
                                               const float* __restrict__ b2) {
    __shared__ float As[64 * 33];
    __shared__ float Bs[32 * 68];
    int t = threadIdx.x;
    int tx = t & 15, ty = t >> 4;
    int n0 = blockIdx.x * 64;
    float acc[4][4] = {};
    for (int k0 = 0; k0 < 512; k0 += 32) {
        for (int i = t; i < 2048; i += 256) {
            int r = i >> 5, k = i & 31;
            As[r * 33 + k] = g_h0[r * 512 + k0 + k];
        }
        for (int i = t; i < 2048; i += 256) {
            int k = i >> 6, n = i & 63;
            int nn = n0 + n;
            Bs[k * 68 + n] = (nn < 6000) ? w2[(k0 + k) * 6000 + nn] : 0.f;
        }
        __syncthreads();
#pragma unroll
        for (int k = 0; k < 32; k++) {
            float a[4], bb[4];
#pragma unroll
            for (int i = 0; i < 4; i++) a[i] = As[(4 * ty + i) * 33 + k];
#pragma unroll
            for (int j = 0; j < 4; j++) bb[j] = Bs[k * 68 + 4 * tx + j];
#pragma unroll
            for (int i = 0; i < 4; i++)
#pragma unroll
                for (int j = 0; j < 4; j++) acc[i][j] = fmaf(a[i], bb[j], acc[i][j]);
        }
        __syncthreads();
    }
#pragma unroll
    for (int i = 0; i < 4; i++) {
        int r = 4 * ty + i;
#pragma unroll
        for (int j = 0; j < 4; j++) {
            int col = n0 + 4 * tx + j;
            if (col < 6000) g_wcode[r * 6000 + col] = acc[i][j] + b2[col];
        }
    }
}

// =============== kernel A (mma.sync tf32): fc1 -> fc2 -> fce/fca ============
#define KA_AS    0
#define KA_B2    33280
#define KA_FC2B  50688
#define KA_FCEB  50944
#define KA_F1W   50976
#define KA_F1B   51744
#define KA_WC    52000
#define KA_TOT   52384

__global__ __launch_bounds__(512, 1) void k_A(
    const float* __restrict__ fc1_w, const float* __restrict__ fc1_b,
    const float* __restrict__ fc2_b,
    const float* __restrict__ fca_b, const float* __restrict__ fce_b) {
    extern __shared__ float sm[];
    uint32_t* AsU  = (uint32_t*)(sm + KA_AS);
    uint32_t* B2U  = (uint32_t*)(sm + KA_B2);
    float*    B2F  = sm + KA_B2;
    float*    fc2bS= sm + KA_FC2B;
    float*    fcebS= sm + KA_FCEB;
    float*    f1w  = sm + KA_F1W;
    float*    f1b  = sm + KA_F1B;
    float*    wcS  = sm + KA_WC;

    const int t = threadIdx.x;
    const int wid = t >> 5, lane = t & 31;
    const int gr = lane >> 2, tg = lane & 3;
    const int row0 = blockIdx.x * 128;

    for (int i = t; i < 768; i += 512) f1w[i] = fc1_w[i];
    if (t < 256) f1b[t] = fc1_b[t];
    if (t < 256) fc2bS[t] = fc2_b[t];
    if (t < 32) fcebS[t] = fce_b[t];
    for (int i = t; i < 384; i += 512) wcS[i] = g_wcode[row0 * 3 + i];
    __syncthreads();

    {
        int r = t >> 2, kb = (t & 3) * 64;
        float w0 = wcS[r * 3 + 0], w1 = wcS[r * 3 + 1], w2 = wcS[r * 3 + 2];
        for (int j = 0; j < 64; j += 4) {
            uint4 u;
            int k = kb + j;
            u.x = f2tf(fmaxf(fmaf(w0, f1w[k+0], fmaf(w1, f1w[256+k+0], fmaf(w2, f1w[512+k+0], f1b[k+0]))), 0.f));
            u.y = f2tf(fmaxf(fmaf(w0, f1w[k+1], fmaf(w1, f1w[256+k+1], fmaf(w2, f1w[512+k+1], f1b[k+1]))), 0.f));
            u.z = f2tf(fmaxf(fmaf(w0, f1w[k+2], fmaf(w1, f1w[256+k+2], fmaf(w2, f1w[512+k+2], f1b[k+2]))), 0.f));
            u.w = f2tf(fmaxf(fmaf(w0, f1w[k+3], fmaf(w1, f1w[256+k+3], fmaf(w2, f1w[512+k+3], f1b[k+3]))), 0.f));
            *(uint4*)&AsU[r * 260 + k] = u;
        }
    }

    {
        int i = t;
        int k = i >> 6, n4 = (i & 63) * 4;
        uint4 q0 = *(const uint4*)&g_w2u[k * 256 + n4];
        uint4 q1 = *(const uint4*)&g_w2u[(k + 8) * 256 + n4];
        uint4 q2 = *(const uint4*)&g_w2u[(k + 16) * 256 + n4];
        uint4 q3 = *(const uint4*)&g_w2u[(k + 24) * 256 + n4];
        __syncthreads();
        *(uint4*)&B2U[k * 260 + n4]        = q0;
        *(uint4*)&B2U[(k + 8) * 260 + n4]  = q1;
        *(uint4*)&B2U[(k + 16) * 260 + n4] = q2;
        *(uint4*)&B2U[(k + 24) * 260 + n4] = q3;
    }
    __syncthreads();

    const int wm = wid & 3, wn = wid >> 2;
    const int m0 = wm * 32, n0 = wn * 64;
    float acc1[16][4] = {};
    for (int c = 0; c < 8; c++) {
        uint4 pf[4];
        if (c < 7) {
            int k = t >> 6, n4 = (t & 63) * 4;
#pragma unroll
            for (int q = 0; q < 4; q++)
                pf[q] = *(const uint4*)&g_w2u[(32 * (c + 1) + k + 8 * q) * 256 + n4];
        }
#pragma unroll
        for (int ks = 0; ks < 4; ks++) {
            int kk = ks * 8;
            int kb = 32 * c + kk;
            uint32_t a[2][4];
#pragma unroll
            for (int mt = 0; mt < 2; mt++) {
                int row = m0 + mt * 16 + gr;
                a[mt][0] = AsU[row * 260 + kb + tg];
                a[mt][1] = AsU[(row + 8) * 260 + kb + tg];
                a[mt][2] = AsU[row * 260 + kb + tg + 4];
                a[mt][3] = AsU[(row + 8) * 260 + kb + tg + 4];
            }
#pragma unroll
            for (int nt = 0; nt < 8; nt++) {
                int col = n0 + nt * 8 + gr;
                uint32_t b[2];
                b[0] = B2U[(kk + tg) * 260 + col];
                b[1] = B2U[(kk + tg + 4) * 260 + col];
#pragma unroll
                for (int mt = 0; mt < 2; mt++) mma8(acc1[mt * 8 + nt], a[mt], b);
            }
        }
        __syncthreads();
        if (c < 7) {
            int k = t >> 6, n4 = (t & 63) * 4;
#pragma unroll
            for (int q = 0; q < 4; q++)
                *(uint4*)&B2U[(k + 8 * q) * 260 + n4] = pf[q];
            __syncthreads();
        }
    }

#pragma unroll
    for (int mt = 0; mt < 2; mt++) {
#pragma unroll
        for (int nt = 0; nt < 8; nt++) {
            int col = n0 + nt * 8 + 2 * tg;
            int r0 = m0 + mt * 16 + gr;
            float b0 = fc2bS[col], b1 = fc2bS[col + 1];
            float* d = acc1[mt * 8 + nt];
            uint2 u0, u1;
            u0.x = f2tf(fmaxf(d[0] + b0, 0.f));
            u0.y = f2tf(fmaxf(d[1] + b1, 0.f));
            u1.x = f2tf(fmaxf(d[2] + b0, 0.f));
            u1.y = f2tf(fmaxf(d[3] + b1, 0.f));
            *(uint2*)&AsU[r0 * 260 + col]       = u0;
            *(uint2*)&AsU[(r0 + 8) * 260 + col] = u1;
        }
    }
    for (int i = t; i < 4096; i += 512) {
        int k = i >> 4, n4 = (i & 15) * 4;
        *(uint4*)&B2U[k * 68 + n4] = *(const uint4*)&g_we2u[k * 64 + n4];
    }
    __syncthreads();

    const int n02 = wn * 16;
    float acc2[4][4] = {};
#pragma unroll 4
    for (int ks = 0; ks < 32; ks++) {
        int kb = ks * 8;
        uint32_t a[2][4];
#pragma unroll
        for (int mt = 0; mt < 2; mt++) {
            int row = m0 + mt * 16 + gr;
            a[mt][0] = AsU[row * 260 + kb + tg];
            a[mt][1] = AsU[(row + 8) * 260 + kb + tg];
            a[mt][2] = AsU[row * 260 + kb + tg + 4];
            a[mt][3] = AsU[(row + 8) * 260 + kb + tg + 4];
        }
#pragma unroll
        for (int nt = 0; nt < 2; nt++) {
            int col = n02 + nt * 8 + gr;
            uint32_t b[2];
            b[0] = B2U[(kb + tg) * 68 + col];
            b[1] = B2U[(kb + tg + 4) * 68 + col];
#pragma unroll
            for (int mt = 0; mt < 2; mt++) mma8(acc2[mt * 2 + nt], a[mt], b);
        }
    }
    __syncthreads();

    float* es = B2F;
#pragma unroll
    for (int mt = 0; mt < 2; mt++) {
#pragma unroll
        for (int nt = 0; nt < 2; nt++) {
            int col = n02 + nt * 8 + 2 * tg;
            int r0 = m0 + mt * 16 + gr;
            float* d = acc2[mt * 2 + nt];
            if (col < 32) {
                float b0 = fcebS[col], b1 = fcebS[col + 1];
                es[r0 * 36 + col]           = d[0] + b0;
                es[r0 * 36 + col + 1]       = d[1] + b1;
                es[(r0 + 8) * 36 + col]     = d[2] + b0;
                es[(r0 + 8) * 36 + col + 1] = d[3] + b1;
            } else if (col == 32) {
                es[r0 * 36 + 32]       = d[0];
                es[(r0 + 8) * 36 + 32] = d[2];
            }
        }
    }
    __syncthreads();
    for (int i = t; i < 1024; i += 512) {
        int r = i >> 3, j4 = (i & 7) * 4;
        float4 vv = *(const float4*)&es[r * 36 + j4];
        *(float4*)&g_e[(size_t)(row0 + r) * 32 + j4] = vv;
    }
    if (t < 128) g_act[row0 + t] = sigmoidf_(es[t * 36 + 32] + fca_b[0]);
}

// ======== kernel B v2: 256 thr, 64-n tile, 2 CTA/SM, ldmatrix, cp.async =====
// smem floats:
#define KB_RT    0          // route [64 n][260 v] = 16640
#define KB_UN    16640      // union: vsS[256][36]=9216 @+0, es[64][36]=2304 @+9216
                            //        later: vc buf0 @+0 (4608), buf1 @+4608 (4608)
#define KB_ACT   28160      // 64
#define KB_RM    28224      // 64*4
#define KB_RS    28480      // 64*4
#define KB_TOT   28736      // floats -> 114944 bytes

__global__ __launch_bounds__(256, 2) void k_B(const float* __restrict__ vc_g,
                                              float* __restrict__ out) {
    extern __shared__ float sm[];
    float*    rtF  = sm + KB_RT;
    uint32_t* rtU  = (uint32_t*)rtF;
    uint32_t* vsU  = (uint32_t*)(sm + KB_UN);
    uint32_t* esU  = (uint32_t*)(sm + KB_UN + 9216);
    float*    actS = sm + KB_ACT;
    float*    redm = sm + KB_RM;
    float*    reds = sm + KB_RS;

    const uint32_t rt_b = smem_u32(rtF);
    const uint32_t un_b = smem_u32(sm + KB_UN);
    const uint32_t es_b = un_b + 9216 * 4;

    const int t = threadIdx.x;
    const int wid = t >> 5, lane = t & 31;
    const int gr = lane >> 2, tg = lane & 3;
    const int lr8 = (lane >> 3) & 1, l7 = lane & 7, lhi = lane >> 4;
    const int n0g = blockIdx.x * 64;
    const int b   = blockIdx.y;
    const float* Avc = vc_g + (size_t)b * CSZ * V_PIX;

    // ---- stage vsS [v][36] (tf32), es [n][36] (tf32), act ----
    for (int i = t; i < 8192; i += 256) {
        int v = i >> 5, e = i & 31;
        vsU[v * 36 + e] = f2tf(g_vs[i]);
    }
    for (int i = t; i < 2048; i += 256) {
        int n = i >> 5, j = i & 31;
        int row = n0g + n;
        float e = (row < N_WRD) ? g_e[(size_t)(b * N_WRD + row) * 32 + j] : 0.f;
        esU[n * 36 + j] = f2tf(e);
    }
    if (t < 64) {
        int row = n0g + t;
        actS[t] = (row < N_WRD) ? g_act[b * N_WRD + row] : 0.f;
    }
    __syncthreads();

    // ---- relation mma: M=64 n, N=256 v, K=32. warps: wm=wid&1, wn=wid>>1 ---
    const int wm = wid & 1, wn = wid >> 1;
    const int m0 = wm * 32, v0 = wn * 64;
    float accr[2][8][4] = {};
#pragma unroll
    for (int ks = 0; ks < 4; ks++) {
        uint32_t aF[2][4];
#pragma unroll
        for (int mt = 0; mt < 2; mt++) {
            uint32_t adr = es_b + (uint32_t)(((m0 + mt * 16 + lr8 * 8 + l7) * 36
                                              + ks * 8 + lhi * 4) * 4);
            ldm_x4(aF[mt], adr);
        }
#pragma unroll
        for (int ntp = 0; ntp < 4; ntp++) {
            uint32_t bF[4];
            uint32_t adr = un_b + (uint32_t)(((v0 + (ntp * 2 + lhi) * 8 + l7) * 36
                                              + ks * 8 + lr8 * 4) * 4);
            ldm_x4(bF, adr);
#pragma unroll
            for (int mt = 0; mt < 2; mt++) {
                mma8(accr[mt][2 * ntp],     aF[mt], bF);
                mma8(accr[mt][2 * ntp + 1], aF[mt], bF + 2);
            }
        }
    }

    // ---- softmax in registers. thread owns 4 n's x 16 v's ----
    // pass: quad-max -> redm
#pragma unroll
    for (int mt = 0; mt < 2; mt++) {
        float mxa = -1e30f, mxb = -1e30f;
#pragma unroll
        for (int nt = 0; nt < 8; nt++) {
            float* d = accr[mt][nt];
            mxa = fmaxf(mxa, fmaxf(d[0], d[1]));
            mxb = fmaxf(mxb, fmaxf(d[2], d[3]));
        }
        mxa = fmaxf(mxa, __shfl_xor_sync(0xffffffffu, mxa, 1));
        mxa = fmaxf(mxa, __shfl_xor_sync(0xffffffffu, mxa, 2));
        mxb = fmaxf(mxb, __shfl_xor_sync(0xffffffffu, mxb, 1));
        mxb = fmaxf(mxb, __shfl_xor_sync(0xffffffffu, mxb, 2));
        if (tg == 0) {
            redm[(m0 + mt * 16 + gr) * 4 + wn] = mxa;
            redm[(m0 + mt * 16 + 8 + gr) * 4 + wn] = mxb;
        }
    }
    __syncthreads();

    // issue cp.async for VC chunks 0 and 1 (overlaps softmax tail)
#pragma unroll
    for (int c = 0; c < 2; c++) {
#pragma unroll
        for (int q = 0; q < 4; q++) {
            int s = t + 256 * q;
            int row = s >> 3, k4 = s & 7;
            uint32_t dst = un_b + (uint32_t)((c * 4608 + row * 36 + k4 * 4) * 4);
            CP_ASYNC16(dst, Avc + row * 256 + c * 32 + k4 * 4);
        }
        CP_COMMIT();
    }

    // pass: exp + quad-sum -> reds
#pragma unroll
    for (int mt = 0; mt < 2; mt++) {
        int na = m0 + mt * 16 + gr, nb = na + 8;
        float ma = fmaxf(fmaxf(redm[na * 4 + 0], redm[na * 4 + 1]),
                         fmaxf(redm[na * 4 + 2], redm[na * 4 + 3]));
        float mb = fmaxf(fmaxf(redm[nb * 4 + 0], redm[nb * 4 + 1]),
                         fmaxf(redm[nb * 4 + 2], redm[nb * 4 + 3]));
        float sa = 0.f, sb = 0.f;
#pragma unroll
        for (int nt = 0; nt < 8; nt++) {
            float* d = accr[mt][nt];
            d[0] = __expf(d[0] - ma); d[1] = __expf(d[1] - ma);
            d[2] = __expf(d[2] - mb); d[3] = __expf(d[3] - mb);
            sa += d[0] + d[1];
            sb += d[2] + d[3];
        }
        sa += __shfl_xor_sync(0xffffffffu, sa, 1);
        sa += __shfl_xor_sync(0xffffffffu, sa, 2);
        sb += __shfl_xor_sync(0xffffffffu, sb, 1);
        sb += __shfl_xor_sync(0xffffffffu, sb, 2);
        if (tg == 0) { reds[na * 4 + wn] = sa; reds[nb * 4 + wn] = sb; }
    }
    __syncthreads();

    // pass: scale by act/sum, convert tf32, store route[n][v] once
#pragma unroll
    for (int mt = 0; mt < 2; mt++) {
        int na = m0 + mt * 16 + gr, nb = na + 8;
        float sA = reds[na * 4 + 0] + reds[na * 4 + 1] + reds[na * 4 + 2] + reds[na * 4 + 3];
        float sB = reds[nb * 4 + 0] + reds[nb * 4 + 1] + reds[nb * 4 + 2] + reds[nb * 4 + 3];
        float scA = actS[na] / sA;
        float scB = actS[nb] / sB;
#pragma unroll
        for (int nt = 0; nt < 8; nt++) {
            int v = v0 + nt * 8 + 2 * tg;
            float* d = accr[mt][nt];
            uint2 ua, ub;
            ua.x = f2tf(d[0] * scA); ua.y = f2tf(d[1] * scA);
            ub.x = f2tf(d[2] * scB); ub.y = f2tf(d[3] * scB);
            *(uint2*)&rtU[na * 260 + v] = ua;
            *(uint2*)&rtU[nb * 260 + v] = ub;
        }
    }
    __syncthreads();

    // ---- out GEMM: M=128 c, N=64 n, K=256 v (8 chunks). warps 4m x 2n ------
    const int wm2 = wid >> 1, wn2 = wid & 1;
    const int c0 = wm2 * 32, n0o = wn2 * 32;
    float acco[2][4][4] = {};
    for (int c = 0; c < 8; c++) {
        if (c < 7) { CP_WAIT1(); } else { CP_WAIT0(); }
        __syncthreads();
        const uint32_t vcb = un_b + (uint32_t)((c & 1) * 4608 * 4);
#pragma unroll
        for (int ks = 0; ks < 4; ks++) {
            uint32_t aF[2][4];
#pragma unroll
            for (int mt = 0; mt < 2; mt++) {
                uint32_t adr = vcb + (uint32_t)(((c0 + mt * 16 + lr8 * 8 + l7) * 36
                                                 + ks * 8 + lhi * 4) * 4);
                ldm_x4(aF[mt], adr);
#pragma unroll
                for (int q = 0; q < 4; q++)
                    aF[mt][q] = f2tf(__uint_as_float(aF[mt][q]));
            }
#pragma unroll
            for (int ntp = 0; ntp < 2; ntp++) {
                uint32_t bF[4];
                uint32_t adr = rt_b + (uint32_t)(((n0o + (ntp * 2 + lhi) * 8 + l7) * 260
                                                  + c * 32 + ks * 8 + lr8 * 4) * 4);
                ldm_x4(bF, adr);
#pragma unroll
                for (int mt = 0; mt < 2; mt++) {
                    mma8(acco[mt][2 * ntp],     aF[mt], bF);
                    mma8(acco[mt][2 * ntp + 1], aF[mt], bF + 2);
                }
            }
        }
        if (c < 6) {
            __syncthreads();   // all warps done with buffer (c&1) before refill
            int cn = c + 2;
#pragma unroll
            for (int q = 0; q < 4; q++) {
                int s = t + 256 * q;
                int row = s >> 3, k4 = s & 7;
                uint32_t dst = un_b + (uint32_t)(((cn & 1) * 4608 + row * 36 + k4 * 4) * 4);
                CP_ASYNC16(dst, Avc + row * 256 + cn * 32 + k4 * 4);
            }
            CP_COMMIT();
        }
    }

    // ---- store out ----
#pragma unroll
    for (int mt = 0; mt < 2; mt++) {
#pragma unroll
        for (int nt = 0; nt < 4; nt++) {
            int r0 = c0 + mt * 16 + gr;
            int ng = n0g + n0o + nt * 8 + 2 * tg;
            float* d = acco[mt][nt];
            if (ng < N_WRD) {
                float2 s0; s0.x = d[0]; s0.y = d[1];
                float2 s1; s1.x = d[2]; s1.y = d[3];
                *(float2*)&out[((size_t)b * CSZ + r0) * N_WRD + ng]     = s0;
                *(float2*)&out[((size_t)b * CSZ + r0 + 8) * N_WRD + ng] = s1;
            }
        }
    }
}

// ---------------- launch --------------------------------------------------
extern "C" void kernel_launch(void* const* d_in, const int* in_sizes, int n_in,
                              void* d_out, int out_size) {
    const float* view_cell = (const float*)d_in[0];
    const float* v         = (const float*)d_in[1];
    const float* w2c_w1    = (const float*)d_in[2];
    const float* w2c_b1    = (const float*)d_in[3];
    const float* w2c_w2    = (const float*)d_in[4];
    const float* w2c_b2    = (const float*)d_in[5];
    const float* fc1_w     = (const float*)d_in[6];
    const float* fc1_b     = (const float*)d_in[7];
    const float* fc2_w     = (const float*)d_in[8];
    const float* fc2_b     = (const float*)d_in[9];
    const float* fca_w     = (const float*)d_in[10];
    const float* fca_b     = (const float*)d_in[11];
    const float* fce_w     = (const float*)d_in[12];
    const float* fce_b     = (const float*)d_in[13];
    const float* vse_w1    = (const float*)d_in[14];
    const float* vse_b1    = (const float*)d_in[15];
    const float* vse_w2    = (const float*)d_in[16];
    const float* vse_b2    = (const float*)d_in[17];
    float* out = (float*)d_out;

    static bool attr_set = false;
    if (!attr_set) {
        cudaFuncSetAttribute(k_A, cudaFuncAttributeMaxDynamicSharedMemorySize, KA_TOT * 4);
        cudaFuncSetAttribute(k_B, cudaFuncAttributeMaxDynamicSharedMemorySize, KB_TOT * 4);
        attr_set = true;
    }

    k_setup<<<352, 256>>>(fc2_w, fce_w, fca_w, v, w2c_w1, w2c_b1,
                          vse_w1, vse_b1, vse_w2, vse_b2);
    k_wcode<<<(6000 + 63) / 64, 256>>>(w2c_w2, w2c_b2);
    k_A<<<(B_SZ * N_WRD) / 128, 512, KA_TOT * 4>>>(fc1_w, fc1_b, fc2_b, fca_b, fce_b);
    dim3 gridB((N_WRD + 63) / 64, B_SZ);
    k_B<<<gridB, 256, KB_TOT * 4>>>(view_cell, out);
}